// round 1
// baseline (speedup 1.0000x reference)
#include <cuda_runtime.h>
#include <math.h>

// ---------------------------------------------------------------------------
// Problem constants
// ---------------------------------------------------------------------------
#define BATCH   2
#define LSEQ    2048
#define DIMC    256
#define DI      512          // d_inner
#define DS      64           // d_state
#define DTR     16           // dt_rank
#define XDBLW   144          // dt_rank + 2*d_state
#define NBLK    4
#define BSZ     64           // block size (DIM/NB)
#define NTOK    (BATCH*LSEQ) // 4096
#define SQRT_INV_8192 0.011048543456039806f
#define LAMBDA_SS 0.01f

// ---------------------------------------------------------------------------
// Scratch (single __device__ array; no allocations anywhere)
// ---------------------------------------------------------------------------
#define O_XN    ((size_t)0)
#define O_XZ    (O_XN   + (size_t)NTOK*DIMC)      // 4096*1024
#define O_XC    (O_XZ   + (size_t)NTOK*2*DI)
#define O_XDBL  (O_XC   + (size_t)NTOK*DI)
#define O_DT    (O_XDBL + (size_t)NTOK*XDBLW)
#define O_Y     (O_DT   + (size_t)NTOK*DI)
#define O_X1    (O_Y    + (size_t)NTOK*DI)
#define O_XN2   (O_X1   + (size_t)NTOK*DIMC)
#define O_FR    (O_XN2  + (size_t)NTOK*DIMC)
#define O_FI    (O_FR   + (size_t)NTOK*DIMC)
#define O_R1    (O_FI   + (size_t)NTOK*DIMC)
#define O_I1    (O_R1   + (size_t)NTOK*DIMC)
#define O_END   (O_I1   + (size_t)NTOK*DIMC)

__device__ float SCRATCH[O_END];

// ---------------------------------------------------------------------------
// LayerNorm: one warp per token (256 channels), 8 tokens per 256-thread block
// ---------------------------------------------------------------------------
__global__ void ln_kernel(const float* __restrict__ x,
                          const float* __restrict__ w,
                          const float* __restrict__ b,
                          float* __restrict__ out) {
    int t = blockIdx.x * 8 + (threadIdx.x >> 5);
    int lane = threadIdx.x & 31;
    const float4* row = (const float4*)(x + (size_t)t * DIMC);
    float4 v0 = row[lane];
    float4 v1 = row[lane + 32];
    float s = v0.x + v0.y + v0.z + v0.w + v1.x + v1.y + v1.z + v1.w;
    #pragma unroll
    for (int off = 16; off; off >>= 1) s += __shfl_xor_sync(0xffffffffu, s, off);
    float m = s * (1.0f / 256.0f);
    float d0 = v0.x - m, d1 = v0.y - m, d2 = v0.z - m, d3 = v0.w - m;
    float d4 = v1.x - m, d5 = v1.y - m, d6 = v1.z - m, d7 = v1.w - m;
    float q = d0*d0 + d1*d1 + d2*d2 + d3*d3 + d4*d4 + d5*d5 + d6*d6 + d7*d7;
    #pragma unroll
    for (int off = 16; off; off >>= 1) q += __shfl_xor_sync(0xffffffffu, q, off);
    float inv = rsqrtf(q * (1.0f / 256.0f) + 1e-5f);
    const float4* w4 = (const float4*)w;
    const float4* b4 = (const float4*)b;
    float4* o4 = (float4*)(out + (size_t)t * DIMC);
    float4 wa = w4[lane], ba = b4[lane];
    float4 wb = w4[lane + 32], bb = b4[lane + 32];
    float4 r0, r1;
    r0.x = d0*inv*wa.x + ba.x; r0.y = d1*inv*wa.y + ba.y;
    r0.z = d2*inv*wa.z + ba.z; r0.w = d3*inv*wa.w + ba.w;
    r1.x = d4*inv*wb.x + bb.x; r1.y = d5*inv*wb.y + bb.y;
    r1.z = d6*inv*wb.z + bb.z; r1.w = d7*inv*wb.w + bb.w;
    o4[lane] = r0; o4[lane + 32] = r1;
}

// ---------------------------------------------------------------------------
// SGEMM: C[M,N] = A[M,K] * W[N,K]^T (+ R[M,N]).  64x64 tile, 256 threads,
// 4x4 per-thread microtile, K-step 16.
// ---------------------------------------------------------------------------
__global__ void sgemm_nt(const float* __restrict__ A,
                         const float* __restrict__ W,
                         const float* __restrict__ R,
                         float* __restrict__ C,
                         int M, int N, int K) {
    __shared__ float As[16 * 64];
    __shared__ float Bs[16 * 64];
    int m0 = blockIdx.y * 64;
    int n0 = blockIdx.x * 64;
    int tid = threadIdx.x;
    int tx = tid & 15, ty = tid >> 4;
    float acc[4][4];
    #pragma unroll
    for (int i = 0; i < 4; i++)
        #pragma unroll
        for (int j = 0; j < 4; j++) acc[i][j] = 0.0f;

    for (int k0 = 0; k0 < K; k0 += 16) {
        #pragma unroll
        for (int i = tid; i < 1024; i += 256) {
            int mm = i >> 4, kk = i & 15;
            int m = m0 + mm, k = k0 + kk;
            As[kk * 64 + mm] = (m < M) ? A[(size_t)m * K + k] : 0.0f;
        }
        #pragma unroll
        for (int i = tid; i < 1024; i += 256) {
            int nn = i >> 4, kk = i & 15;
            int n = n0 + nn, k = k0 + kk;
            Bs[kk * 64 + nn] = (n < N) ? W[(size_t)n * K + k] : 0.0f;
        }
        __syncthreads();
        #pragma unroll
        for (int kk = 0; kk < 16; kk++) {
            float4 av = ((const float4*)(As + kk * 64))[ty];
            float4 bv = ((const float4*)(Bs + kk * 64))[tx];
            float a[4] = {av.x, av.y, av.z, av.w};
            float bb2[4] = {bv.x, bv.y, bv.z, bv.w};
            #pragma unroll
            for (int i = 0; i < 4; i++)
                #pragma unroll
                for (int j = 0; j < 4; j++) acc[i][j] += a[i] * bb2[j];
        }
        __syncthreads();
    }
    #pragma unroll
    for (int i = 0; i < 4; i++) {
        int m = m0 + ty * 4 + i;
        if (m >= M) continue;
        #pragma unroll
        for (int j = 0; j < 4; j++) {
            int n = n0 + tx * 4 + j;
            if (n >= N) continue;
            float v = acc[i][j];
            if (R) v += R[(size_t)m * N + n];
            C[(size_t)m * N + n] = v;
        }
    }
}

// ---------------------------------------------------------------------------
// Depthwise causal conv (k=4) + bias + SiLU.  xz[:, 0:512] -> xc
// ---------------------------------------------------------------------------
__global__ void conv_silu_kernel(const float* __restrict__ xz,
                                 const float* __restrict__ cw,
                                 const float* __restrict__ cb,
                                 float* __restrict__ xc) {
    int idx = blockIdx.x * 256 + threadIdx.x;   // NTOK*DI
    int d = idx & (DI - 1);
    int bt = idx >> 9;
    int b = bt >> 11;
    int l = bt & (LSEQ - 1);
    float acc = cb[d];
    #pragma unroll
    for (int k = 0; k < 4; k++) {
        int ls = l + k - 3;
        if (ls >= 0)
            acc += xz[((size_t)((b << 11) | ls)) * (2 * DI) + d] * cw[d * 4 + k];
    }
    float sg = 1.0f / (1.0f + __expf(-acc));
    xc[(size_t)bt * DI + d] = acc * sg;
}

// ---------------------------------------------------------------------------
// dt = softplus(xdbl[:, :16] @ dt_proj_w^T + dt_proj_b)
// ---------------------------------------------------------------------------
__global__ void dt_kernel(const float* __restrict__ xdbl,
                          const float* __restrict__ w,
                          const float* __restrict__ bias,
                          float* __restrict__ dt) {
    int idx = blockIdx.x * 256 + threadIdx.x;   // NTOK*DI
    int d = idx & (DI - 1);
    int bt = idx >> 9;
    const float* r = xdbl + (size_t)bt * XDBLW;
    const float* wr = w + d * DTR;
    float acc = bias[d];
    #pragma unroll
    for (int i = 0; i < DTR; i++) acc += r[i] * wr[i];
    dt[idx] = (acc > 20.0f) ? acc : log1pf(expf(acc));
}

// ---------------------------------------------------------------------------
// Selective scan.  One warp per (b, d) channel; lane owns states s, s+32.
// B/C rows staged in smem per 64-step chunk (shared across the 8 d-warps).
// Fused D-skip and silu(z) gating.
// ---------------------------------------------------------------------------
#define TCHUNK 64
__global__ void scan_kernel(const float* __restrict__ xdbl,
                            const float* __restrict__ dt,
                            const float* __restrict__ xc,
                            const float* __restrict__ xz,
                            const float* __restrict__ A_log,
                            const float* __restrict__ Dvec,
                            float* __restrict__ y) {
    __shared__ float sB[TCHUNK][64];
    __shared__ float sC[TCHUNK][64];
    int b = blockIdx.x >> 6;                 // 64 blocks per batch
    int dbase = (blockIdx.x & 63) * 8;
    int wid = threadIdx.x >> 5;
    int lane = threadIdx.x & 31;
    int d = dbase + wid;
    float A0 = -expf(A_log[d * DS + lane]);
    float A1 = -expf(A_log[d * DS + lane + 32]);
    float Dd = Dvec[d];
    float h0 = 0.0f, h1 = 0.0f;

    for (int t0 = 0; t0 < LSEQ; t0 += TCHUNK) {
        __syncthreads();
        for (int i = threadIdx.x; i < TCHUNK * 128; i += 256) {
            int tt = i >> 7;
            int c = i & 127;
            float v = xdbl[(size_t)(b * LSEQ + t0 + tt) * XDBLW + DTR + c];
            if (c < 64) sB[tt][c] = v; else sC[tt][c - 64] = v;
        }
        __syncthreads();
        #pragma unroll 4
        for (int tt = 0; tt < TCHUNK; tt++) {
            int bt = b * LSEQ + t0 + tt;
            float dtv = dt[(size_t)bt * DI + d];
            float xcv = xc[(size_t)bt * DI + d];
            float dA0 = __expf(dtv * A0);
            float dA1 = __expf(dtv * A1);
            float du = dtv * xcv;
            h0 = dA0 * h0 + du * sB[tt][lane];
            h1 = dA1 * h1 + du * sB[tt][lane + 32];
            float yv = h0 * sC[tt][lane] + h1 * sC[tt][lane + 32];
            #pragma unroll
            for (int off = 16; off; off >>= 1)
                yv += __shfl_xor_sync(0xffffffffu, yv, off);
            if (lane == 0) {
                float zv = xz[(size_t)bt * (2 * DI) + DI + d];
                float g = zv / (1.0f + __expf(-zv));
                y[(size_t)bt * DI + d] = (yv + xcv * Dd) * g;
            }
        }
    }
}

// ---------------------------------------------------------------------------
// Forward 4-point DFT over the NB axis (real input -> complex), fold in the
// full fft2-ortho scale 1/sqrt(8192).
// ---------------------------------------------------------------------------
__global__ void dft4_fwd_kernel(const float* __restrict__ x,
                                float* __restrict__ outR,
                                float* __restrict__ outI) {
    int idx = blockIdx.x * 256 + threadIdx.x;   // NTOK*BSZ
    int bn = idx >> 6;
    int s = idx & 63;
    size_t o = (size_t)bn * DIMC + s;
    float v0 = x[o], v1 = x[o + 64], v2 = x[o + 128], v3 = x[o + 192];
    const float sc = SQRT_INV_8192;
    float e = v0 + v2, f = v0 - v2, g = v1 + v3, h = v1 - v3;
    outR[o]        = (e + g) * sc;  outI[o]        = 0.0f;
    outR[o + 64]   = f * sc;        outI[o + 64]   = -h * sc;
    outR[o + 128]  = (e - g) * sc;  outI[o + 128]  = 0.0f;
    outR[o + 192]  = f * sc;        outI[o + 192]  = h * sc;
}

// ---------------------------------------------------------------------------
// 2048-point radix-2 Stockham FFT along n (in place per column).
// One block per (b, k, s) column; 512 threads; ping-pong smem.
// sign = -1 forward, +1 inverse (unscaled).
// ---------------------------------------------------------------------------
__global__ void fft2048_kernel(float* __restrict__ dR,
                               float* __restrict__ dI,
                               float sign) {
    __shared__ float sr[2][2048];
    __shared__ float si[2][2048];
    int col = blockIdx.x;                 // [0, BATCH*256)
    int b = col >> 8;
    int rem = col & 255;
    size_t base = (size_t)b * LSEQ * DIMC + rem;
    int tid = threadIdx.x;                // 512

    for (int i = tid; i < 2048; i += 512) {
        sr[0][i] = dR[base + (size_t)i * DIMC];
        si[0][i] = dI[base + (size_t)i * DIMC];
    }
    __syncthreads();

    int src = 0;
    for (int p = 0; p < 11; p++) {
        int Ns = 1 << p;
        int dst = src ^ 1;
        for (int j = tid; j < 1024; j += 512) {
            float ar = sr[src][j],        ai = si[src][j];
            float br = sr[src][j + 1024], bi = si[src][j + 1024];
            int jm = j & (Ns - 1);
            float ang = sign * 3.14159265358979323846f * (float)jm / (float)Ns;
            float wi, wr;
            sincosf(ang, &wi, &wr);
            float tr = br * wr - bi * wi;
            float ti = br * wi + bi * wr;
            int idxD = ((j >> p) << (p + 1)) + jm;
            sr[dst][idxD]      = ar + tr;  si[dst][idxD]      = ai + ti;
            sr[dst][idxD + Ns] = ar - tr;  si[dst][idxD + Ns] = ai - ti;
        }
        __syncthreads();
        src = dst;
    }
    for (int i = tid; i < 2048; i += 512) {
        dR[base + (size_t)i * DIMC] = sr[src][i];
        dI[base + (size_t)i * DIMC] = si[src][i];
    }
}

// ---------------------------------------------------------------------------
// EinFFT complex block matmul layer.
// outR = act(inR*W0 - inI*W1 + b0); outI = act(inR*W1 + inI*W0 + b1)
// mode 0 = relu, 1 = softshrink.  8 rows per block, thread = (k, o).
// ---------------------------------------------------------------------------
__global__ void cmul_kernel(const float* __restrict__ inR,
                            const float* __restrict__ inI,
                            const float* __restrict__ cw,
                            const float* __restrict__ cb,
                            float* __restrict__ outR,
                            float* __restrict__ outI,
                            int mode) {
    __shared__ float sR[8 * 256];
    __shared__ float sI[8 * 256];
    int row0 = blockIdx.x * 8;
    int tid = threadIdx.x;
    for (int i = tid; i < 2048; i += 256) {
        sR[i] = inR[(size_t)row0 * DIMC + i];
        sI[i] = inI[(size_t)row0 * DIMC + i];
    }
    __syncthreads();
    int k = tid >> 6, o = tid & 63;
    const float* w0 = cw + k * 4096;
    const float* w1 = cw + 16384 + k * 4096;
    float bR = cb[k * 64 + o];
    float bI = cb[256 + k * 64 + o];
    float aR[8], aI[8];
    #pragma unroll
    for (int r = 0; r < 8; r++) { aR[r] = bR; aI[r] = bI; }
    for (int d = 0; d < 64; d++) {
        float wa = w0[d * 64 + o];
        float wb = w1[d * 64 + o];
        int sb = k * 64 + d;
        #pragma unroll
        for (int r = 0; r < 8; r++) {
            float xr = sR[r * 256 + sb];
            float xi = sI[r * 256 + sb];
            aR[r] += xr * wa - xi * wb;
            aI[r] += xr * wb + xi * wa;
        }
    }
    #pragma unroll
    for (int r = 0; r < 8; r++) {
        float vR = aR[r], vI = aI[r];
        if (mode == 0) {
            vR = fmaxf(vR, 0.0f);
            vI = fmaxf(vI, 0.0f);
        } else {
            vR = (vR > LAMBDA_SS) ? vR - LAMBDA_SS
                 : ((vR < -LAMBDA_SS) ? vR + LAMBDA_SS : 0.0f);
            vI = (vI > LAMBDA_SS) ? vI - LAMBDA_SS
                 : ((vI < -LAMBDA_SS) ? vI + LAMBDA_SS : 0.0f);
        }
        outR[(size_t)(row0 + r) * DIMC + tid] = vR;
        outI[(size_t)(row0 + r) * DIMC + tid] = vI;
    }
}

// ---------------------------------------------------------------------------
// Inverse 4-point DFT over NB axis, take real part, scale, add residual x1.
// ---------------------------------------------------------------------------
__global__ void dft4_inv_res_kernel(const float* __restrict__ gr,
                                    const float* __restrict__ gi,
                                    const float* __restrict__ x1,
                                    float* __restrict__ out) {
    int idx = blockIdx.x * 256 + threadIdx.x;   // NTOK*BSZ
    int bn = idx >> 6;
    int s = idx & 63;
    size_t o = (size_t)bn * DIMC + s;
    float r0 = gr[o], r1 = gr[o + 64], r2 = gr[o + 128], r3 = gr[o + 192];
    float i1 = gi[o + 64], i3 = gi[o + 192];
    const float sc = SQRT_INV_8192;
    float y0 = (r0 + r1 + r2 + r3) * sc;
    float y1 = (r0 - i1 - r2 + i3) * sc;
    float y2 = (r0 - r1 + r2 - r3) * sc;
    float y3 = (r0 + i1 - r2 - i3) * sc;
    out[o]       = x1[o]       + y0;
    out[o + 64]  = x1[o + 64]  + y1;
    out[o + 128] = x1[o + 128] + y2;
    out[o + 192] = x1[o + 192] + y3;
}

// ---------------------------------------------------------------------------
// Launch
// ---------------------------------------------------------------------------
extern "C" void kernel_launch(void* const* d_in, const int* in_sizes, int n_in,
                              void* d_out, int out_size) {
    const float* x         = (const float*)d_in[0];
    const float* norm1_w   = (const float*)d_in[1];
    const float* norm1_b   = (const float*)d_in[2];
    const float* in_proj_w = (const float*)d_in[3];
    const float* conv_w    = (const float*)d_in[4];
    const float* conv_b    = (const float*)d_in[5];
    const float* x_proj_w  = (const float*)d_in[6];
    const float* dt_proj_w = (const float*)d_in[7];
    const float* dt_proj_b = (const float*)d_in[8];
    const float* A_log     = (const float*)d_in[9];
    const float* Dvec      = (const float*)d_in[10];
    const float* out_proj_w= (const float*)d_in[11];
    const float* norm2_w   = (const float*)d_in[12];
    const float* norm2_b   = (const float*)d_in[13];
    const float* cw1       = (const float*)d_in[14];
    const float* cb1       = (const float*)d_in[15];
    const float* cw2       = (const float*)d_in[16];
    const float* cb2       = (const float*)d_in[17];
    float* out = (float*)d_out;

    void* sp = nullptr;
    cudaGetSymbolAddress(&sp, SCRATCH);
    float* S = (float*)sp;
    float* s_xn   = S + O_XN;
    float* s_xz   = S + O_XZ;
    float* s_xc   = S + O_XC;
    float* s_xdbl = S + O_XDBL;
    float* s_dt   = S + O_DT;
    float* s_y    = S + O_Y;
    float* s_x1   = S + O_X1;
    float* s_xn2  = S + O_XN2;
    float* s_fr   = S + O_FR;
    float* s_fi   = S + O_FI;
    float* s_r1   = S + O_R1;
    float* s_i1   = S + O_I1;

    // 1) LN1
    ln_kernel<<<NTOK / 8, 256>>>(x, norm1_w, norm1_b, s_xn);
    // 2) in_proj: (4096,256) x (1024,256)^T
    sgemm_nt<<<dim3((2 * DI) / 64, NTOK / 64), 256>>>(s_xn, in_proj_w, nullptr,
                                                      s_xz, NTOK, 2 * DI, DIMC);
    // 3) conv + silu
    conv_silu_kernel<<<(NTOK * DI) / 256, 256>>>(s_xz, conv_w, conv_b, s_xc);
    // 4) x_proj: (4096,512) x (144,512)^T
    sgemm_nt<<<dim3((XDBLW + 63) / 64, NTOK / 64), 256>>>(s_xc, x_proj_w, nullptr,
                                                          s_xdbl, NTOK, XDBLW, DI);
    // 5) dt
    dt_kernel<<<(NTOK * DI) / 256, 256>>>(s_xdbl, dt_proj_w, dt_proj_b, s_dt);
    // 6) selective scan (fused D-skip + silu(z) gate)
    scan_kernel<<<BATCH * (DI / 8), 256>>>(s_xdbl, s_dt, s_xc, s_xz, A_log, Dvec, s_y);
    // 7) out_proj + residual
    sgemm_nt<<<dim3(DIMC / 64, NTOK / 64), 256>>>(s_y, out_proj_w, x,
                                                  s_x1, NTOK, DIMC, DI);
    // 8) LN2
    ln_kernel<<<NTOK / 8, 256>>>(s_x1, norm2_w, norm2_b, s_xn2);
    // 9) forward 4-pt DFT over NB (+ ortho scale)
    dft4_fwd_kernel<<<(NTOK * BSZ) / 256, 256>>>(s_xn2, s_fr, s_fi);
    // 10) forward 2048-pt FFT along n
    fft2048_kernel<<<BATCH * 256, 512>>>(s_fr, s_fi, -1.0f);
    // 11) layer 1 (relu)
    cmul_kernel<<<NTOK / 8, 256>>>(s_fr, s_fi, cw1, cb1, s_r1, s_i1, 0);
    // 12) layer 2 (softshrink) -> reuse fr/fi
    cmul_kernel<<<NTOK / 8, 256>>>(s_r1, s_i1, cw2, cb2, s_fr, s_fi, 1);
    // 13) inverse 2048-pt FFT along n
    fft2048_kernel<<<BATCH * 256, 512>>>(s_fr, s_fi, 1.0f);
    // 14) inverse 4-pt DFT, real part, scale, residual -> out
    dft4_inv_res_kernel<<<(NTOK * BSZ) / 256, 256>>>(s_fr, s_fi, s_x1, out);
}

// round 2
// speedup vs baseline: 2.0945x; 2.0945x over previous
#include <cuda_runtime.h>
#include <math.h>

// ---------------------------------------------------------------------------
// Problem constants
// ---------------------------------------------------------------------------
#define BATCH   2
#define LSEQ    2048
#define DIMC    256
#define DI      512          // d_inner
#define DS      64           // d_state
#define DTR     16           // dt_rank
#define XDBLW   144          // dt_rank + 2*d_state
#define NTOK    (BATCH*LSEQ) // 4096
#define SQRT_INV_8192 0.011048543456039806f
#define LAMBDA_SS 0.01f
#define PI_F 3.14159265358979323846f

// ---------------------------------------------------------------------------
// Scratch (single __device__ array; no allocations anywhere)
// ---------------------------------------------------------------------------
#define O_XN    ((size_t)0)
#define O_XZ    (O_XN   + (size_t)NTOK*DIMC)
#define O_XC    (O_XZ   + (size_t)NTOK*2*DI)
#define O_XDBL  (O_XC   + (size_t)NTOK*DI)
#define O_DT    (O_XDBL + (size_t)NTOK*XDBLW)
#define O_Y     (O_DT   + (size_t)NTOK*DI)
#define O_X1    (O_Y    + (size_t)NTOK*DI)
#define O_XN2   (O_X1   + (size_t)NTOK*DIMC)
#define O_FR    (O_XN2  + (size_t)NTOK*DIMC)
#define O_FI    (O_FR   + (size_t)NTOK*DIMC)
#define O_END   (O_FI   + (size_t)NTOK*DIMC)

__device__ float SCRATCH[O_END];

// ---------------------------------------------------------------------------
// LayerNorm: one warp per token (256 channels), 8 tokens per 256-thread block
// ---------------------------------------------------------------------------
__global__ void ln_kernel(const float* __restrict__ x,
                          const float* __restrict__ w,
                          const float* __restrict__ b,
                          float* __restrict__ out) {
    int t = blockIdx.x * 8 + (threadIdx.x >> 5);
    int lane = threadIdx.x & 31;
    const float4* row = (const float4*)(x + (size_t)t * DIMC);
    float4 v0 = row[lane];
    float4 v1 = row[lane + 32];
    float s = v0.x + v0.y + v0.z + v0.w + v1.x + v1.y + v1.z + v1.w;
    #pragma unroll
    for (int off = 16; off; off >>= 1) s += __shfl_xor_sync(0xffffffffu, s, off);
    float m = s * (1.0f / 256.0f);
    float d0 = v0.x - m, d1 = v0.y - m, d2 = v0.z - m, d3 = v0.w - m;
    float d4 = v1.x - m, d5 = v1.y - m, d6 = v1.z - m, d7 = v1.w - m;
    float q = d0*d0 + d1*d1 + d2*d2 + d3*d3 + d4*d4 + d5*d5 + d6*d6 + d7*d7;
    #pragma unroll
    for (int off = 16; off; off >>= 1) q += __shfl_xor_sync(0xffffffffu, q, off);
    float inv = rsqrtf(q * (1.0f / 256.0f) + 1e-5f);
    const float4* w4 = (const float4*)w;
    const float4* b4 = (const float4*)b;
    float4* o4 = (float4*)(out + (size_t)t * DIMC);
    float4 wa = w4[lane], ba = b4[lane];
    float4 wb = w4[lane + 32], bb = b4[lane + 32];
    float4 r0, r1;
    r0.x = d0*inv*wa.x + ba.x; r0.y = d1*inv*wa.y + ba.y;
    r0.z = d2*inv*wa.z + ba.z; r0.w = d3*inv*wa.w + ba.w;
    r1.x = d4*inv*wb.x + bb.x; r1.y = d5*inv*wb.y + bb.y;
    r1.z = d6*inv*wb.z + bb.z; r1.w = d7*inv*wb.w + bb.w;
    o4[lane] = r0; o4[lane + 32] = r1;
}

// ---------------------------------------------------------------------------
// SGEMM: C[M,N] = A[M,K] * W[N,K]^T (+ R[M,N]).
// 64x64 tile, 256 threads, 4x4 microtile, K-step 16, double-buffered smem,
// float4 global loads. M multiple of 64, K multiple of 16 (guaranteed here).
// ---------------------------------------------------------------------------
#define SPAD 68
__global__ void __launch_bounds__(256) sgemm_nt(const float* __restrict__ A,
                                                const float* __restrict__ W,
                                                const float* __restrict__ R,
                                                float* __restrict__ C,
                                                int M, int N, int K) {
    __shared__ float As[2][16][SPAD];
    __shared__ float Bs[2][16][SPAD];
    int m0 = blockIdx.y * 64;
    int n0 = blockIdx.x * 64;
    int tid = threadIdx.x;
    int lr = tid >> 2;       // 0..63 (tile row)
    int lq = tid & 3;        // k-quad
    int tx = tid & 15, ty = tid >> 4;
    float acc[4][4] = {};

    float4 a4, b4;
    // preload tile 0
    a4 = *(const float4*)(A + (size_t)(m0 + lr) * K + lq * 4);
    b4 = (n0 + lr < N) ? *(const float4*)(W + (size_t)(n0 + lr) * K + lq * 4)
                       : make_float4(0.f, 0.f, 0.f, 0.f);
    As[0][lq*4+0][lr] = a4.x; As[0][lq*4+1][lr] = a4.y;
    As[0][lq*4+2][lr] = a4.z; As[0][lq*4+3][lr] = a4.w;
    Bs[0][lq*4+0][lr] = b4.x; Bs[0][lq*4+1][lr] = b4.y;
    Bs[0][lq*4+2][lr] = b4.z; Bs[0][lq*4+3][lr] = b4.w;
    __syncthreads();

    int nIt = K >> 4;
    for (int it = 0; it < nIt; it++) {
        int buf = it & 1;
        if (it + 1 < nIt) {
            int k0 = (it + 1) << 4;
            a4 = *(const float4*)(A + (size_t)(m0 + lr) * K + k0 + lq * 4);
            b4 = (n0 + lr < N) ? *(const float4*)(W + (size_t)(n0 + lr) * K + k0 + lq * 4)
                               : make_float4(0.f, 0.f, 0.f, 0.f);
        }
        #pragma unroll
        for (int kk = 0; kk < 16; kk++) {
            float4 av = *(const float4*)(&As[buf][kk][ty * 4]);
            float4 bv = *(const float4*)(&Bs[buf][kk][tx * 4]);
            float a[4] = {av.x, av.y, av.z, av.w};
            float bb2[4] = {bv.x, bv.y, bv.z, bv.w};
            #pragma unroll
            for (int i = 0; i < 4; i++)
                #pragma unroll
                for (int j = 0; j < 4; j++)
                    acc[i][j] = fmaf(a[i], bb2[j], acc[i][j]);
        }
        if (it + 1 < nIt) {
            int nb = buf ^ 1;
            As[nb][lq*4+0][lr] = a4.x; As[nb][lq*4+1][lr] = a4.y;
            As[nb][lq*4+2][lr] = a4.z; As[nb][lq*4+3][lr] = a4.w;
            Bs[nb][lq*4+0][lr] = b4.x; Bs[nb][lq*4+1][lr] = b4.y;
            Bs[nb][lq*4+2][lr] = b4.z; Bs[nb][lq*4+3][lr] = b4.w;
        }
        __syncthreads();
    }

    #pragma unroll
    for (int i = 0; i < 4; i++) {
        int m = m0 + ty * 4 + i;
        #pragma unroll
        for (int j = 0; j < 4; j++) {
            int n = n0 + tx * 4 + j;
            if (n >= N) continue;
            float v = acc[i][j];
            if (R) v += R[(size_t)m * N + n];
            C[(size_t)m * N + n] = v;
        }
    }
}

// ---------------------------------------------------------------------------
// Depthwise causal conv (k=4) + bias + SiLU.  xz[:, 0:512] -> xc
// ---------------------------------------------------------------------------
__global__ void conv_silu_kernel(const float* __restrict__ xz,
                                 const float* __restrict__ cw,
                                 const float* __restrict__ cb,
                                 float* __restrict__ xc) {
    int idx = blockIdx.x * 256 + threadIdx.x;   // NTOK*DI
    int d = idx & (DI - 1);
    int bt = idx >> 9;
    int b = bt >> 11;
    int l = bt & (LSEQ - 1);
    float acc = cb[d];
    #pragma unroll
    for (int k = 0; k < 4; k++) {
        int ls = l + k - 3;
        if (ls >= 0)
            acc += xz[((size_t)((b << 11) | ls)) * (2 * DI) + d] * cw[d * 4 + k];
    }
    float sg = 1.0f / (1.0f + __expf(-acc));
    xc[(size_t)bt * DI + d] = acc * sg;
}

// ---------------------------------------------------------------------------
// dt = softplus(xdbl[:, :16] @ dt_proj_w^T + dt_proj_b)
// ---------------------------------------------------------------------------
__global__ void dt_kernel(const float* __restrict__ xdbl,
                          const float* __restrict__ w,
                          const float* __restrict__ bias,
                          float* __restrict__ dt) {
    int idx = blockIdx.x * 256 + threadIdx.x;   // NTOK*DI
    int d = idx & (DI - 1);
    int bt = idx >> 9;
    const float* r = xdbl + (size_t)bt * XDBLW;
    const float* wr = w + d * DTR;
    float acc = bias[d];
    #pragma unroll
    for (int i = 0; i < DTR; i++) acc += r[i] * wr[i];
    dt[idx] = (acc > 20.0f) ? acc : log1pf(expf(acc));
}

// ---------------------------------------------------------------------------
// Selective scan.  One warp per (b, d) channel; lane owns states s, s+32.
// All per-step inputs (B, C, dt, xc, z) staged through smem per 64-step
// chunk with coalesced loads; y staged out through smem.
// ---------------------------------------------------------------------------
#define TCHUNK 64
__global__ void __launch_bounds__(256) scan_kernel(
        const float* __restrict__ xdbl,
        const float* __restrict__ dt,
        const float* __restrict__ xc,
        const float* __restrict__ xz,
        const float* __restrict__ A_log,
        const float* __restrict__ Dvec,
        float* __restrict__ y) {
    __shared__ float sB[TCHUNK][64];
    __shared__ float sC[TCHUNK][64];
    __shared__ float sdt[TCHUNK][8];
    __shared__ float sxc[TCHUNK][8];
    __shared__ float sz[TCHUNK][8];
    __shared__ float sy[TCHUNK][8];
    int b = blockIdx.x >> 6;
    int dbase = (blockIdx.x & 63) * 8;
    int wid = threadIdx.x >> 5;
    int lane = threadIdx.x & 31;
    int d = dbase + wid;
    float A0 = -__expf(A_log[d * DS + lane]);
    float A1 = -__expf(A_log[d * DS + lane + 32]);
    float Dd = Dvec[d];
    float h0 = 0.0f, h1 = 0.0f;

    for (int t0 = 0; t0 < LSEQ; t0 += TCHUNK) {
        for (int i = threadIdx.x; i < TCHUNK * 128; i += 256) {
            int tt = i >> 7;
            int c = i & 127;
            float v = xdbl[(size_t)(b * LSEQ + t0 + tt) * XDBLW + DTR + c];
            if (c < 64) sB[tt][c] = v; else sC[tt][c - 64] = v;
        }
        for (int i = threadIdx.x; i < TCHUNK * 8; i += 256) {
            int tt = i >> 3, di = i & 7;
            size_t bt = (size_t)(b * LSEQ + t0 + tt);
            sdt[tt][di] = dt[bt * DI + dbase + di];
            sxc[tt][di] = xc[bt * DI + dbase + di];
            sz[tt][di]  = xz[bt * (2 * DI) + DI + dbase + di];
        }
        __syncthreads();
        #pragma unroll 4
        for (int tt = 0; tt < TCHUNK; tt++) {
            float dtv = sdt[tt][wid];
            float xcv = sxc[tt][wid];
            float dA0 = __expf(dtv * A0);
            float dA1 = __expf(dtv * A1);
            float du = dtv * xcv;
            h0 = fmaf(dA0, h0, du * sB[tt][lane]);
            h1 = fmaf(dA1, h1, du * sB[tt][lane + 32]);
            float yv = h0 * sC[tt][lane] + h1 * sC[tt][lane + 32];
            #pragma unroll
            for (int off = 16; off; off >>= 1)
                yv += __shfl_xor_sync(0xffffffffu, yv, off);
            if (lane == 0) {
                float zv = sz[tt][wid];
                float g = zv / (1.0f + __expf(-zv));
                sy[tt][wid] = (yv + xcv * Dd) * g;
            }
        }
        __syncthreads();
        for (int i = threadIdx.x; i < TCHUNK * 8; i += 256) {
            int tt = i >> 3, di = i & 7;
            y[(size_t)(b * LSEQ + t0 + tt) * DI + dbase + di] = sy[tt][di];
        }
        __syncthreads();
    }
}

// ---------------------------------------------------------------------------
// Forward 4-point DFT over the NB axis (real input -> complex), fold in the
// full fft2-ortho scale 1/sqrt(8192).
// ---------------------------------------------------------------------------
__global__ void dft4_fwd_kernel(const float* __restrict__ x,
                                float* __restrict__ outR,
                                float* __restrict__ outI) {
    int idx = blockIdx.x * 256 + threadIdx.x;   // NTOK*64
    int bn = idx >> 6;
    int s = idx & 63;
    size_t o = (size_t)bn * DIMC + s;
    float v0 = x[o], v1 = x[o + 64], v2 = x[o + 128], v3 = x[o + 192];
    const float sc = SQRT_INV_8192;
    float e = v0 + v2, f = v0 - v2, g = v1 + v3, h = v1 - v3;
    outR[o]        = (e + g) * sc;  outI[o]        = 0.0f;
    outR[o + 64]   = f * sc;        outI[o + 64]   = -h * sc;
    outR[o + 128]  = (e - g) * sc;  outI[o + 128]  = 0.0f;
    outR[o + 192]  = f * sc;        outI[o + 192]  = h * sc;
}

// ---------------------------------------------------------------------------
// 2048-pt FFT along n, in-place (no ping-pong):
//   forward:  DIF (natural -> bit-reversed)
//   inverse:  DIT (bit-reversed -> natural)
// The permutation cancels because everything in between is pointwise in n.
// 2 columns per block, 256 threads, __sincosf twiddles.
// ---------------------------------------------------------------------------
__global__ void __launch_bounds__(256) fft2048_kernel(float* __restrict__ dR,
                                                      float* __restrict__ dI,
                                                      int inverse) {
    __shared__ float sr[2][2048];
    __shared__ float si[2][2048];
    int gc0 = blockIdx.x * 2;           // global column 0..511
    int tid = threadIdx.x;
    size_t base0 = ((size_t)(gc0 >> 8) * LSEQ) * DIMC + (gc0 & 255);
    size_t base1 = ((size_t)((gc0 + 1) >> 8) * LSEQ) * DIMC + ((gc0 + 1) & 255);

    for (int e = tid; e < 4096; e += 256) {
        int col = e >> 11, n = e & 2047;
        size_t a = (col ? base1 : base0) + (size_t)n * DIMC;
        sr[col][n] = dR[a];
        si[col][n] = dI[a];
    }
    __syncthreads();

    if (!inverse) {
        #pragma unroll
        for (int hb = 10; hb >= 0; hb--) {
            int half = 1 << hb;
            float th = -PI_F / (float)half;
            for (int e = tid; e < 2048; e += 256) {
                int col = e >> 10, idx = e & 1023;
                int j = idx & (half - 1);
                int pos = ((idx >> hb) << (hb + 1)) + j;
                float ar = sr[col][pos],        ai = si[col][pos];
                float br = sr[col][pos + half], bi = si[col][pos + half];
                float wi, wr;
                __sincosf(th * (float)j, &wi, &wr);
                float xr = ar - br, xi = ai - bi;
                sr[col][pos] = ar + br;  si[col][pos] = ai + bi;
                sr[col][pos + half] = xr * wr - xi * wi;
                si[col][pos + half] = xr * wi + xi * wr;
            }
            __syncthreads();
        }
    } else {
        #pragma unroll
        for (int hb = 0; hb <= 10; hb++) {
            int half = 1 << hb;
            float th = PI_F / (float)half;
            for (int e = tid; e < 2048; e += 256) {
                int col = e >> 10, idx = e & 1023;
                int j = idx & (half - 1);
                int pos = ((idx >> hb) << (hb + 1)) + j;
                float ar = sr[col][pos],        ai = si[col][pos];
                float br = sr[col][pos + half], bi = si[col][pos + half];
                float wi, wr;
                __sincosf(th * (float)j, &wi, &wr);
                float tr = br * wr - bi * wi;
                float ti = br * wi + bi * wr;
                sr[col][pos] = ar + tr;         si[col][pos] = ai + ti;
                sr[col][pos + half] = ar - tr;  si[col][pos + half] = ai - ti;
            }
            __syncthreads();
        }
    }

    for (int e = tid; e < 4096; e += 256) {
        int col = e >> 11, n = e & 2047;
        size_t a = (col ? base1 : base0) + (size_t)n * DIMC;
        dR[a] = sr[col][n];
        dI[a] = si[col][n];
    }
}

// ---------------------------------------------------------------------------
// EinFFT MLP: both complex block-matmul layers fused (relu then softshrink),
// r1/i1 kept in smem.  8 rows per block, thread = (k, o).  In-place on fR/fI.
// ---------------------------------------------------------------------------
__global__ void __launch_bounds__(256) einfft_mlp_kernel(
        float* __restrict__ fR, float* __restrict__ fI,
        const float* __restrict__ cw1, const float* __restrict__ cb1,
        const float* __restrict__ cw2, const float* __restrict__ cb2) {
    __shared__ float sR[2048], sI[2048];
    __shared__ float tR[2048], tI[2048];
    int row0 = blockIdx.x * 8;
    int tid = threadIdx.x;
    for (int i = tid; i < 2048; i += 256) {
        sR[i] = fR[(size_t)row0 * DIMC + i];
        sI[i] = fI[(size_t)row0 * DIMC + i];
    }
    __syncthreads();
    int k = tid >> 6, o = tid & 63;

    // layer 1 (relu)
    {
        const float* w0 = cw1 + k * 4096;
        const float* w1 = cw1 + 16384 + k * 4096;
        float bR = cb1[k * 64 + o];
        float bI = cb1[256 + k * 64 + o];
        float aR[8], aI[8];
        #pragma unroll
        for (int r = 0; r < 8; r++) { aR[r] = bR; aI[r] = bI; }
        for (int d = 0; d < 64; d++) {
            float wa = w0[d * 64 + o];
            float wb = w1[d * 64 + o];
            int sb = k * 64 + d;
            #pragma unroll
            for (int r = 0; r < 8; r++) {
                float xr = sR[r * 256 + sb];
                float xi = sI[r * 256 + sb];
                aR[r] = fmaf(xr, wa, fmaf(-xi, wb, aR[r]));
                aI[r] = fmaf(xr, wb, fmaf( xi, wa, aI[r]));
            }
        }
        #pragma unroll
        for (int r = 0; r < 8; r++) {
            tR[r * 256 + tid] = fmaxf(aR[r], 0.0f);
            tI[r * 256 + tid] = fmaxf(aI[r], 0.0f);
        }
    }
    __syncthreads();

    // layer 2 (softshrink) -> global
    {
        const float* w0 = cw2 + k * 4096;
        const float* w1 = cw2 + 16384 + k * 4096;
        float bR = cb2[k * 64 + o];
        float bI = cb2[256 + k * 64 + o];
        float aR[8], aI[8];
        #pragma unroll
        for (int r = 0; r < 8; r++) { aR[r] = bR; aI[r] = bI; }
        for (int d = 0; d < 64; d++) {
            float wa = w0[d * 64 + o];
            float wb = w1[d * 64 + o];
            int sb = k * 64 + d;
            #pragma unroll
            for (int r = 0; r < 8; r++) {
                float xr = tR[r * 256 + sb];
                float xi = tI[r * 256 + sb];
                aR[r] = fmaf(xr, wa, fmaf(-xi, wb, aR[r]));
                aI[r] = fmaf(xr, wb, fmaf( xi, wa, aI[r]));
            }
        }
        #pragma unroll
        for (int r = 0; r < 8; r++) {
            float vR = aR[r], vI = aI[r];
            vR = (vR > LAMBDA_SS) ? vR - LAMBDA_SS
                 : ((vR < -LAMBDA_SS) ? vR + LAMBDA_SS : 0.0f);
            vI = (vI > LAMBDA_SS) ? vI - LAMBDA_SS
                 : ((vI < -LAMBDA_SS) ? vI + LAMBDA_SS : 0.0f);
            fR[(size_t)(row0 + r) * DIMC + tid] = vR;
            fI[(size_t)(row0 + r) * DIMC + tid] = vI;
        }
    }
}

// ---------------------------------------------------------------------------
// Inverse 4-point DFT over NB axis, take real part, scale, add residual x1.
// ---------------------------------------------------------------------------
__global__ void dft4_inv_res_kernel(const float* __restrict__ gr,
                                    const float* __restrict__ gi,
                                    const float* __restrict__ x1,
                                    float* __restrict__ out) {
    int idx = blockIdx.x * 256 + threadIdx.x;   // NTOK*64
    int bn = idx >> 6;
    int s = idx & 63;
    size_t o = (size_t)bn * DIMC + s;
    float r0 = gr[o], r1 = gr[o + 64], r2 = gr[o + 128], r3 = gr[o + 192];
    float i1 = gi[o + 64], i3 = gi[o + 192];
    const float sc = SQRT_INV_8192;
    float y0 = (r0 + r1 + r2 + r3) * sc;
    float y1 = (r0 - i1 - r2 + i3) * sc;
    float y2 = (r0 - r1 + r2 - r3) * sc;
    float y3 = (r0 + i1 - r2 - i3) * sc;
    out[o]       = x1[o]       + y0;
    out[o + 64]  = x1[o + 64]  + y1;
    out[o + 128] = x1[o + 128] + y2;
    out[o + 192] = x1[o + 192] + y3;
}

// ---------------------------------------------------------------------------
// Launch
// ---------------------------------------------------------------------------
extern "C" void kernel_launch(void* const* d_in, const int* in_sizes, int n_in,
                              void* d_out, int out_size) {
    const float* x         = (const float*)d_in[0];
    const float* norm1_w   = (const float*)d_in[1];
    const float* norm1_b   = (const float*)d_in[2];
    const float* in_proj_w = (const float*)d_in[3];
    const float* conv_w    = (const float*)d_in[4];
    const float* conv_b    = (const float*)d_in[5];
    const float* x_proj_w  = (const float*)d_in[6];
    const float* dt_proj_w = (const float*)d_in[7];
    const float* dt_proj_b = (const float*)d_in[8];
    const float* A_log     = (const float*)d_in[9];
    const float* Dvec      = (const float*)d_in[10];
    const float* out_proj_w= (const float*)d_in[11];
    const float* norm2_w   = (const float*)d_in[12];
    const float* norm2_b   = (const float*)d_in[13];
    const float* cw1       = (const float*)d_in[14];
    const float* cb1       = (const float*)d_in[15];
    const float* cw2       = (const float*)d_in[16];
    const float* cb2       = (const float*)d_in[17];
    float* out = (float*)d_out;

    void* sp = nullptr;
    cudaGetSymbolAddress(&sp, SCRATCH);
    float* S = (float*)sp;
    float* s_xn   = S + O_XN;
    float* s_xz   = S + O_XZ;
    float* s_xc   = S + O_XC;
    float* s_xdbl = S + O_XDBL;
    float* s_dt   = S + O_DT;
    float* s_y    = S + O_Y;
    float* s_x1   = S + O_X1;
    float* s_xn2  = S + O_XN2;
    float* s_fr   = S + O_FR;
    float* s_fi   = S + O_FI;

    // 1) LN1
    ln_kernel<<<NTOK / 8, 256>>>(x, norm1_w, norm1_b, s_xn);
    // 2) in_proj: (4096,256) x (1024,256)^T
    sgemm_nt<<<dim3((2 * DI) / 64, NTOK / 64), 256>>>(s_xn, in_proj_w, nullptr,
                                                      s_xz, NTOK, 2 * DI, DIMC);
    // 3) conv + silu
    conv_silu_kernel<<<(NTOK * DI) / 256, 256>>>(s_xz, conv_w, conv_b, s_xc);
    // 4) x_proj: (4096,512) x (144,512)^T
    sgemm_nt<<<dim3((XDBLW + 63) / 64, NTOK / 64), 256>>>(s_xc, x_proj_w, nullptr,
                                                          s_xdbl, NTOK, XDBLW, DI);
    // 5) dt
    dt_kernel<<<(NTOK * DI) / 256, 256>>>(s_xdbl, dt_proj_w, dt_proj_b, s_dt);
    // 6) selective scan (fused D-skip + silu(z) gate)
    scan_kernel<<<BATCH * (DI / 8), 256>>>(s_xdbl, s_dt, s_xc, s_xz, A_log, Dvec, s_y);
    // 7) out_proj + residual
    sgemm_nt<<<dim3(DIMC / 64, NTOK / 64), 256>>>(s_y, out_proj_w, x,
                                                  s_x1, NTOK, DIMC, DI);
    // 8) LN2
    ln_kernel<<<NTOK / 8, 256>>>(s_x1, norm2_w, norm2_b, s_xn2);
    // 9) forward 4-pt DFT over NB (+ ortho scale)
    dft4_fwd_kernel<<<(NTOK * 64) / 256, 256>>>(s_xn2, s_fr, s_fi);
    // 10) forward 2048-pt FFT (DIF, natural -> bit-reversed)
    fft2048_kernel<<<256, 256>>>(s_fr, s_fi, 0);
    // 11+12) fused EinFFT MLP (relu + softshrink), in-place on fr/fi
    einfft_mlp_kernel<<<NTOK / 8, 256>>>(s_fr, s_fi, cw1, cb1, cw2, cb2);
    // 13) inverse 2048-pt FFT (DIT, bit-reversed -> natural)
    fft2048_kernel<<<256, 256>>>(s_fr, s_fi, 1);
    // 14) inverse 4-pt DFT, real part, scale, residual -> out
    dft4_inv_res_kernel<<<(NTOK * 64) / 256, 256>>>(s_fr, s_fi, s_x1, out);
}

// round 3
// speedup vs baseline: 2.3384x; 1.1164x over previous
#include <cuda_runtime.h>
#include <math.h>

// ---------------------------------------------------------------------------
// Problem constants
// ---------------------------------------------------------------------------
#define BATCH   2
#define LSEQ    2048
#define DIMC    256
#define DI      512          // d_inner
#define DS      64           // d_state
#define DTR     16           // dt_rank
#define XDBLW   144          // dt_rank + 2*d_state
#define NTOK    (BATCH*LSEQ) // 4096
#define SQRT_INV_8192 0.011048543456039806f
#define LAMBDA_SS 0.01f
#define PI_F 3.14159265358979323846f

// ---------------------------------------------------------------------------
// Scratch (single __device__ array; no allocations anywhere)
// ---------------------------------------------------------------------------
#define O_XN    ((size_t)0)
#define O_XZ    (O_XN   + (size_t)NTOK*DIMC)
#define O_XC    (O_XZ   + (size_t)NTOK*2*DI)
#define O_XDBL  (O_XC   + (size_t)NTOK*DI)
#define O_DT    (O_XDBL + (size_t)NTOK*XDBLW)
#define O_Y     (O_DT   + (size_t)NTOK*DI)
#define O_X1    (O_Y    + (size_t)NTOK*DI)
#define O_XN2   (O_X1   + (size_t)NTOK*DIMC)
#define O_FR    (O_XN2  + (size_t)NTOK*DIMC)
#define O_FI    (O_FR   + (size_t)NTOK*DIMC)
#define O_END   (O_FI   + (size_t)NTOK*DIMC)

__device__ float SCRATCH[O_END];

// ---------------------------------------------------------------------------
// LayerNorm: one warp per token (256 channels), 8 tokens per 256-thread block
// ---------------------------------------------------------------------------
__global__ void ln_kernel(const float* __restrict__ x,
                          const float* __restrict__ w,
                          const float* __restrict__ b,
                          float* __restrict__ out) {
    int t = blockIdx.x * 8 + (threadIdx.x >> 5);
    int lane = threadIdx.x & 31;
    const float4* row = (const float4*)(x + (size_t)t * DIMC);
    float4 v0 = row[lane];
    float4 v1 = row[lane + 32];
    float s = v0.x + v0.y + v0.z + v0.w + v1.x + v1.y + v1.z + v1.w;
    #pragma unroll
    for (int off = 16; off; off >>= 1) s += __shfl_xor_sync(0xffffffffu, s, off);
    float m = s * (1.0f / 256.0f);
    float d0 = v0.x - m, d1 = v0.y - m, d2 = v0.z - m, d3 = v0.w - m;
    float d4 = v1.x - m, d5 = v1.y - m, d6 = v1.z - m, d7 = v1.w - m;
    float q = d0*d0 + d1*d1 + d2*d2 + d3*d3 + d4*d4 + d5*d5 + d6*d6 + d7*d7;
    #pragma unroll
    for (int off = 16; off; off >>= 1) q += __shfl_xor_sync(0xffffffffu, q, off);
    float inv = rsqrtf(q * (1.0f / 256.0f) + 1e-5f);
    const float4* w4 = (const float4*)w;
    const float4* b4 = (const float4*)b;
    float4* o4 = (float4*)(out + (size_t)t * DIMC);
    float4 wa = w4[lane], ba = b4[lane];
    float4 wb = w4[lane + 32], bb = b4[lane + 32];
    float4 r0, r1;
    r0.x = d0*inv*wa.x + ba.x; r0.y = d1*inv*wa.y + ba.y;
    r0.z = d2*inv*wa.z + ba.z; r0.w = d3*inv*wa.w + ba.w;
    r1.x = d4*inv*wb.x + bb.x; r1.y = d5*inv*wb.y + bb.y;
    r1.z = d6*inv*wb.z + bb.z; r1.w = d7*inv*wb.w + bb.w;
    o4[lane] = r0; o4[lane + 32] = r1;
}

// ---------------------------------------------------------------------------
// tf32 tensor-core GEMM: C[M,N] = A[M,K] * W[N,K]^T (+ R[M,N]).
// 128x64 block tile, BK=16, 256 threads = 8 warps (4m x 2n), warp tile 32x32
// via 2x4 mma.sync.m16n8k8.tf32.  Double-buffered smem, stride 20 (conflict-
// free fragment loads).  M % 128 == 0, K % 16 == 0 guaranteed.
// ---------------------------------------------------------------------------
#define GBM 128
#define GBN 64
#define ASTR 20

__device__ __forceinline__ unsigned f2tf(float x) {
    unsigned r;
    asm("cvt.rna.tf32.f32 %0, %1;" : "=r"(r) : "f"(x));
    return r;
}
__device__ __forceinline__ float4 cvt4(float4 v) {
    float4 o;
    o.x = __uint_as_float(f2tf(v.x));
    o.y = __uint_as_float(f2tf(v.y));
    o.z = __uint_as_float(f2tf(v.z));
    o.w = __uint_as_float(f2tf(v.w));
    return o;
}
__device__ __forceinline__ void mma_tf32(float* c, const unsigned* a, const unsigned* b) {
    asm volatile(
        "mma.sync.aligned.m16n8k8.row.col.f32.tf32.tf32.f32 "
        "{%0,%1,%2,%3}, {%4,%5,%6,%7}, {%8,%9}, {%0,%1,%2,%3};"
        : "+f"(c[0]), "+f"(c[1]), "+f"(c[2]), "+f"(c[3])
        : "r"(a[0]), "r"(a[1]), "r"(a[2]), "r"(a[3]), "r"(b[0]), "r"(b[1]));
}

__global__ void __launch_bounds__(256) gemm_tf32(const float* __restrict__ A,
                                                 const float* __restrict__ W,
                                                 const float* __restrict__ R,
                                                 float* __restrict__ C,
                                                 int M, int N, int K) {
    __shared__ float As[2][GBM * ASTR];
    __shared__ float Bs[2][GBN * ASTR];
    int m0 = blockIdx.y * GBM;
    int n0 = blockIdx.x * GBN;
    int tid = threadIdx.x;
    int wid = tid >> 5, lane = tid & 31;
    int wm = (wid & 3) * 32;
    int wn = (wid >> 2) * 32;
    int gid = lane >> 2;       // 0..7
    int tig = lane & 3;        // 0..3
    int ar = tid >> 1, ak = (tid & 1) * 8;
    int br = tid >> 2, bk = (tid & 3) * 4;

    float acc[2][4][4];
    #pragma unroll
    for (int mi = 0; mi < 2; mi++)
        #pragma unroll
        for (int ni = 0; ni < 4; ni++)
            #pragma unroll
            for (int q = 0; q < 4; q++) acc[mi][ni][q] = 0.0f;

    float4 a4a, a4b, b4;
    // preload tile 0
    a4a = *(const float4*)(A + (size_t)(m0 + ar) * K + ak);
    a4b = *(const float4*)(A + (size_t)(m0 + ar) * K + ak + 4);
    b4 = (n0 + br < N) ? *(const float4*)(W + (size_t)(n0 + br) * K + bk)
                       : make_float4(0.f, 0.f, 0.f, 0.f);
    *(float4*)(&As[0][ar * ASTR + ak])     = cvt4(a4a);
    *(float4*)(&As[0][ar * ASTR + ak + 4]) = cvt4(a4b);
    *(float4*)(&Bs[0][br * ASTR + bk])     = cvt4(b4);
    __syncthreads();

    int nIt = K >> 4;
    for (int it = 0; it < nIt; it++) {
        int buf = it & 1;
        if (it + 1 < nIt) {
            int k0 = (it + 1) << 4;
            a4a = *(const float4*)(A + (size_t)(m0 + ar) * K + k0 + ak);
            a4b = *(const float4*)(A + (size_t)(m0 + ar) * K + k0 + ak + 4);
            b4 = (n0 + br < N) ? *(const float4*)(W + (size_t)(n0 + br) * K + k0 + bk)
                               : make_float4(0.f, 0.f, 0.f, 0.f);
        }
        #pragma unroll
        for (int ks = 0; ks < 2; ks++) {
            int k8 = ks * 8;
            unsigned afr[2][4], bfr[4][2];
            #pragma unroll
            for (int mi = 0; mi < 2; mi++) {
                int rb = wm + mi * 16 + gid;
                afr[mi][0] = __float_as_uint(As[buf][(rb)     * ASTR + k8 + tig]);
                afr[mi][1] = __float_as_uint(As[buf][(rb + 8) * ASTR + k8 + tig]);
                afr[mi][2] = __float_as_uint(As[buf][(rb)     * ASTR + k8 + tig + 4]);
                afr[mi][3] = __float_as_uint(As[buf][(rb + 8) * ASTR + k8 + tig + 4]);
            }
            #pragma unroll
            for (int ni = 0; ni < 4; ni++) {
                int cb = wn + ni * 8 + gid;
                bfr[ni][0] = __float_as_uint(Bs[buf][cb * ASTR + k8 + tig]);
                bfr[ni][1] = __float_as_uint(Bs[buf][cb * ASTR + k8 + tig + 4]);
            }
            #pragma unroll
            for (int mi = 0; mi < 2; mi++)
                #pragma unroll
                for (int ni = 0; ni < 4; ni++)
                    mma_tf32(acc[mi][ni], afr[mi], bfr[ni]);
        }
        if (it + 1 < nIt) {
            int nb = buf ^ 1;
            *(float4*)(&As[nb][ar * ASTR + ak])     = cvt4(a4a);
            *(float4*)(&As[nb][ar * ASTR + ak + 4]) = cvt4(a4b);
            *(float4*)(&Bs[nb][br * ASTR + bk])     = cvt4(b4);
        }
        __syncthreads();
    }

    // epilogue: c0:(r,c) c1:(r,c+1) c2:(r+8,c) c3:(r+8,c+1)
    #pragma unroll
    for (int mi = 0; mi < 2; mi++) {
        int row = m0 + wm + mi * 16 + gid;
        #pragma unroll
        for (int ni = 0; ni < 4; ni++) {
            int col = n0 + wn + ni * 8 + tig * 2;
            if (col < N) {
                float v0 = acc[mi][ni][0];
                float v2 = acc[mi][ni][2];
                if (R) { v0 += R[(size_t)row * N + col]; v2 += R[(size_t)(row + 8) * N + col]; }
                C[(size_t)row * N + col] = v0;
                C[(size_t)(row + 8) * N + col] = v2;
            }
            if (col + 1 < N) {
                float v1 = acc[mi][ni][1];
                float v3 = acc[mi][ni][3];
                if (R) { v1 += R[(size_t)row * N + col + 1]; v3 += R[(size_t)(row + 8) * N + col + 1]; }
                C[(size_t)row * N + col + 1] = v1;
                C[(size_t)(row + 8) * N + col + 1] = v3;
            }
        }
    }
}

// ---------------------------------------------------------------------------
// Depthwise causal conv (k=4) + bias + SiLU.  xz[:, 0:512] -> xc
// ---------------------------------------------------------------------------
__global__ void conv_silu_kernel(const float* __restrict__ xz,
                                 const float* __restrict__ cw,
                                 const float* __restrict__ cb,
                                 float* __restrict__ xc) {
    int idx = blockIdx.x * 256 + threadIdx.x;   // NTOK*DI
    int d = idx & (DI - 1);
    int bt = idx >> 9;
    int b = bt >> 11;
    int l = bt & (LSEQ - 1);
    float acc = cb[d];
    #pragma unroll
    for (int k = 0; k < 4; k++) {
        int ls = l + k - 3;
        if (ls >= 0)
            acc += xz[((size_t)((b << 11) | ls)) * (2 * DI) + d] * cw[d * 4 + k];
    }
    float sg = 1.0f / (1.0f + __expf(-acc));
    xc[(size_t)bt * DI + d] = acc * sg;
}

// ---------------------------------------------------------------------------
// dt = softplus(xdbl[:, :16] @ dt_proj_w^T + dt_proj_b)
// ---------------------------------------------------------------------------
__global__ void dt_kernel(const float* __restrict__ xdbl,
                          const float* __restrict__ w,
                          const float* __restrict__ bias,
                          float* __restrict__ dt) {
    int idx = blockIdx.x * 256 + threadIdx.x;   // NTOK*DI
    int d = idx & (DI - 1);
    int bt = idx >> 9;
    const float* r = xdbl + (size_t)bt * XDBLW;
    const float* wr = w + d * DTR;
    float acc = bias[d];
    #pragma unroll
    for (int i = 0; i < DTR; i++) acc += r[i] * wr[i];
    dt[idx] = (acc > 20.0f) ? acc : __logf(1.0f + __expf(acc));
}

// ---------------------------------------------------------------------------
// Selective scan.  One warp per (b, d) channel; lane owns states s, s+32.
// All per-step inputs staged through smem per 64-step chunk (coalesced).
// ---------------------------------------------------------------------------
#define TCHUNK 64
__global__ void __launch_bounds__(256) scan_kernel(
        const float* __restrict__ xdbl,
        const float* __restrict__ dt,
        const float* __restrict__ xc,
        const float* __restrict__ xz,
        const float* __restrict__ A_log,
        const float* __restrict__ Dvec,
        float* __restrict__ y) {
    __shared__ float sB[TCHUNK][64];
    __shared__ float sC[TCHUNK][64];
    __shared__ float sdt[TCHUNK][8];
    __shared__ float sxc[TCHUNK][8];
    __shared__ float sz[TCHUNK][8];
    __shared__ float sy[TCHUNK][8];
    int b = blockIdx.x >> 6;
    int dbase = (blockIdx.x & 63) * 8;
    int wid = threadIdx.x >> 5;
    int lane = threadIdx.x & 31;
    int d = dbase + wid;
    float A0 = -__expf(A_log[d * DS + lane]);
    float A1 = -__expf(A_log[d * DS + lane + 32]);
    float Dd = Dvec[d];
    float h0 = 0.0f, h1 = 0.0f;

    for (int t0 = 0; t0 < LSEQ; t0 += TCHUNK) {
        for (int i = threadIdx.x; i < TCHUNK * 128; i += 256) {
            int tt = i >> 7;
            int c = i & 127;
            float v = xdbl[(size_t)(b * LSEQ + t0 + tt) * XDBLW + DTR + c];
            if (c < 64) sB[tt][c] = v; else sC[tt][c - 64] = v;
        }
        for (int i = threadIdx.x; i < TCHUNK * 8; i += 256) {
            int tt = i >> 3, di = i & 7;
            size_t bt = (size_t)(b * LSEQ + t0 + tt);
            sdt[tt][di] = dt[bt * DI + dbase + di];
            sxc[tt][di] = xc[bt * DI + dbase + di];
            sz[tt][di]  = xz[bt * (2 * DI) + DI + dbase + di];
        }
        __syncthreads();
        #pragma unroll 4
        for (int tt = 0; tt < TCHUNK; tt++) {
            float dtv = sdt[tt][wid];
            float xcv = sxc[tt][wid];
            float dA0 = __expf(dtv * A0);
            float dA1 = __expf(dtv * A1);
            float du = dtv * xcv;
            h0 = fmaf(dA0, h0, du * sB[tt][lane]);
            h1 = fmaf(dA1, h1, du * sB[tt][lane + 32]);
            float yv = h0 * sC[tt][lane] + h1 * sC[tt][lane + 32];
            #pragma unroll
            for (int off = 16; off; off >>= 1)
                yv += __shfl_xor_sync(0xffffffffu, yv, off);
            if (lane == 0) {
                float zv = sz[tt][wid];
                float g = zv / (1.0f + __expf(-zv));
                sy[tt][wid] = (yv + xcv * Dd) * g;
            }
        }
        __syncthreads();
        for (int i = threadIdx.x; i < TCHUNK * 8; i += 256) {
            int tt = i >> 3, di = i & 7;
            y[(size_t)(b * LSEQ + t0 + tt) * DI + dbase + di] = sy[tt][di];
        }
        __syncthreads();
    }
}

// ---------------------------------------------------------------------------
// Forward 2048-pt FFT (DIF, natural -> bit-reversed), real input.
// 8 channels per block (coalesced global I/O), padded smem stride 2049.
// ---------------------------------------------------------------------------
#define FSTR 2049
#define FFT_SMEM (2 * 8 * FSTR * 4)

__global__ void __launch_bounds__(512) fft_fwd_kernel(const float* __restrict__ xin,
                                                      float* __restrict__ dR,
                                                      float* __restrict__ dI) {
    extern __shared__ float sm[];
    float* sr = sm;
    float* si = sm + 8 * FSTR;
    int b = blockIdx.x >> 5;
    int c0 = (blockIdx.x & 31) * 8;
    size_t base = (size_t)b * LSEQ * DIMC + c0;
    int tid = threadIdx.x;

    for (int t = tid; t < 8 * 2048; t += 512) {
        int n = t >> 3, j = t & 7;
        sr[j * FSTR + n] = xin[base + (size_t)n * DIMC + j];
        si[j * FSTR + n] = 0.0f;
    }
    __syncthreads();

    #pragma unroll
    for (int hb = 10; hb >= 0; hb--) {
        int half = 1 << hb;
        float th = -PI_F / (float)half;
        for (int e = tid; e < 8192; e += 512) {
            int col = e >> 10, idx = e & 1023;
            int j = idx & (half - 1);
            int pos = ((idx >> hb) << (hb + 1)) + j;
            float* cr = sr + col * FSTR;
            float* ci = si + col * FSTR;
            float ar = cr[pos],        ai = ci[pos];
            float br = cr[pos + half], bi = ci[pos + half];
            float wi, wr;
            __sincosf(th * (float)j, &wi, &wr);
            float xr = ar - br, xi = ai - bi;
            cr[pos] = ar + br;  ci[pos] = ai + bi;
            cr[pos + half] = xr * wr - xi * wi;
            ci[pos + half] = xr * wi + xi * wr;
        }
        __syncthreads();
    }

    for (int t = tid; t < 8 * 2048; t += 512) {
        int n = t >> 3, j = t & 7;
        dR[base + (size_t)n * DIMC + j] = sr[j * FSTR + n];
        dI[base + (size_t)n * DIMC + j] = si[j * FSTR + n];
    }
}

// ---------------------------------------------------------------------------
// Inverse 2048-pt FFT (DIT, bit-reversed -> natural); output = real part
// + residual x1, written straight to out.
// ---------------------------------------------------------------------------
__global__ void __launch_bounds__(512) fft_inv_kernel(const float* __restrict__ dR,
                                                      const float* __restrict__ dI,
                                                      const float* __restrict__ x1,
                                                      float* __restrict__ out) {
    extern __shared__ float sm[];
    float* sr = sm;
    float* si = sm + 8 * FSTR;
    int b = blockIdx.x >> 5;
    int c0 = (blockIdx.x & 31) * 8;
    size_t base = (size_t)b * LSEQ * DIMC + c0;
    int tid = threadIdx.x;

    for (int t = tid; t < 8 * 2048; t += 512) {
        int n = t >> 3, j = t & 7;
        sr[j * FSTR + n] = dR[base + (size_t)n * DIMC + j];
        si[j * FSTR + n] = dI[base + (size_t)n * DIMC + j];
    }
    __syncthreads();

    #pragma unroll
    for (int hb = 0; hb <= 10; hb++) {
        int half = 1 << hb;
        float th = PI_F / (float)half;
        for (int e = tid; e < 8192; e += 512) {
            int col = e >> 10, idx = e & 1023;
            int j = idx & (half - 1);
            int pos = ((idx >> hb) << (hb + 1)) + j;
            float* cr = sr + col * FSTR;
            float* ci = si + col * FSTR;
            float ar = cr[pos],        ai = ci[pos];
            float br = cr[pos + half], bi = ci[pos + half];
            float wi, wr;
            __sincosf(th * (float)j, &wi, &wr);
            float tr = br * wr - bi * wi;
            float ti = br * wi + bi * wr;
            cr[pos] = ar + tr;         ci[pos] = ai + ti;
            cr[pos + half] = ar - tr;  ci[pos + half] = ai - ti;
        }
        __syncthreads();
    }

    for (int t = tid; t < 8 * 2048; t += 512) {
        int n = t >> 3, j = t & 7;
        size_t a = base + (size_t)n * DIMC + j;
        out[a] = x1[a] + sr[j * FSTR + n];
    }
}

// ---------------------------------------------------------------------------
// EinFFT MLP with DFT4/IDFT4 over the NB axis folded in (FFT_n and DFT4_NB
// commute; everything between them is pointwise in n).
// Layer1 relu, layer2 softshrink.  8 rows/block, in-place on fR/fI.
// ---------------------------------------------------------------------------
__global__ void __launch_bounds__(256) einfft_mlp_kernel(
        float* __restrict__ fR, float* __restrict__ fI,
        const float* __restrict__ cw1, const float* __restrict__ cb1,
        const float* __restrict__ cw2, const float* __restrict__ cb2) {
    __shared__ float sR[2048], sI[2048];
    __shared__ float tR[2048], tI[2048];
    int row0 = blockIdx.x * 8;
    int tid = threadIdx.x;
    for (int i = tid; i < 2048; i += 256) {
        sR[i] = fR[(size_t)row0 * DIMC + i];
        sI[i] = fI[(size_t)row0 * DIMC + i];
    }
    __syncthreads();

    // forward DFT4 over NB (complex), scaled by sc
    const float sc = SQRT_INV_8192;
    #pragma unroll
    for (int g = tid; g < 512; g += 256) {
        int r = g >> 6, s = g & 63;
        int p = r * 256 + s;
        float r0 = sR[p],       i0 = sI[p];
        float r1 = sR[p + 64],  i1 = sI[p + 64];
        float r2 = sR[p + 128], i2 = sI[p + 128];
        float r3 = sR[p + 192], i3 = sI[p + 192];
        sR[p]       = (r0 + r1 + r2 + r3) * sc;
        sI[p]       = (i0 + i1 + i2 + i3) * sc;
        sR[p + 64]  = (r0 + i1 - r2 - i3) * sc;
        sI[p + 64]  = (i0 - r1 - i2 + r3) * sc;
        sR[p + 128] = (r0 - r1 + r2 - r3) * sc;
        sI[p + 128] = (i0 - i1 + i2 - i3) * sc;
        sR[p + 192] = (r0 - i1 - r2 + i3) * sc;
        sI[p + 192] = (i0 + r1 - i2 - r3) * sc;
    }
    __syncthreads();

    int k = tid >> 6, o = tid & 63;

    // layer 1 (relu)
    {
        const float* w0 = cw1 + k * 4096;
        const float* w1 = cw1 + 16384 + k * 4096;
        float bR = cb1[k * 64 + o];
        float bI = cb1[256 + k * 64 + o];
        float aR[8], aI[8];
        #pragma unroll
        for (int r = 0; r < 8; r++) { aR[r] = bR; aI[r] = bI; }
        for (int d = 0; d < 64; d++) {
            float wa = w0[d * 64 + o];
            float wb = w1[d * 64 + o];
            int sb = k * 64 + d;
            #pragma unroll
            for (int r = 0; r < 8; r++) {
                float xr = sR[r * 256 + sb];
                float xi = sI[r * 256 + sb];
                aR[r] = fmaf(xr, wa, fmaf(-xi, wb, aR[r]));
                aI[r] = fmaf(xr, wb, fmaf( xi, wa, aI[r]));
            }
        }
        #pragma unroll
        for (int r = 0; r < 8; r++) {
            tR[r * 256 + tid] = fmaxf(aR[r], 0.0f);
            tI[r * 256 + tid] = fmaxf(aI[r], 0.0f);
        }
    }
    __syncthreads();

    // layer 2 (softshrink) -> back into sR/sI
    {
        const float* w0 = cw2 + k * 4096;
        const float* w1 = cw2 + 16384 + k * 4096;
        float bR = cb2[k * 64 + o];
        float bI = cb2[256 + k * 64 + o];
        float aR[8], aI[8];
        #pragma unroll
        for (int r = 0; r < 8; r++) { aR[r] = bR; aI[r] = bI; }
        for (int d = 0; d < 64; d++) {
            float wa = w0[d * 64 + o];
            float wb = w1[d * 64 + o];
            int sb = k * 64 + d;
            #pragma unroll
            for (int r = 0; r < 8; r++) {
                float xr = tR[r * 256 + sb];
                float xi = tI[r * 256 + sb];
                aR[r] = fmaf(xr, wa, fmaf(-xi, wb, aR[r]));
                aI[r] = fmaf(xr, wb, fmaf( xi, wa, aI[r]));
            }
        }
        #pragma unroll
        for (int r = 0; r < 8; r++) {
            float vR = aR[r], vI = aI[r];
            vR = (vR > LAMBDA_SS) ? vR - LAMBDA_SS
                 : ((vR < -LAMBDA_SS) ? vR + LAMBDA_SS : 0.0f);
            vI = (vI > LAMBDA_SS) ? vI - LAMBDA_SS
                 : ((vI < -LAMBDA_SS) ? vI + LAMBDA_SS : 0.0f);
            sR[r * 256 + tid] = vR;
            sI[r * 256 + tid] = vI;
        }
    }
    __syncthreads();

    // inverse DFT4 over NB (complex), scaled by sc
    #pragma unroll
    for (int g = tid; g < 512; g += 256) {
        int r = g >> 6, s = g & 63;
        int p = r * 256 + s;
        float R0 = sR[p],       I0 = sI[p];
        float R1 = sR[p + 64],  I1 = sI[p + 64];
        float R2 = sR[p + 128], I2 = sI[p + 128];
        float R3 = sR[p + 192], I3 = sI[p + 192];
        sR[p]       = (R0 + R1 + R2 + R3) * sc;
        sI[p]       = (I0 + I1 + I2 + I3) * sc;
        sR[p + 64]  = (R0 - I1 - R2 + I3) * sc;
        sI[p + 64]  = (I0 + R1 - I2 - R3) * sc;
        sR[p + 128] = (R0 - R1 + R2 - R3) * sc;
        sI[p + 128] = (I0 - I1 + I2 - I3) * sc;
        sR[p + 192] = (R0 + I1 - R2 - I3) * sc;
        sI[p + 192] = (I0 - R1 - I2 + R3) * sc;
    }
    __syncthreads();

    for (int i = tid; i < 2048; i += 256) {
        fR[(size_t)row0 * DIMC + i] = sR[i];
        fI[(size_t)row0 * DIMC + i] = sI[i];
    }
}

// ---------------------------------------------------------------------------
// Launch
// ---------------------------------------------------------------------------
extern "C" void kernel_launch(void* const* d_in, const int* in_sizes, int n_in,
                              void* d_out, int out_size) {
    const float* x         = (const float*)d_in[0];
    const float* norm1_w   = (const float*)d_in[1];
    const float* norm1_b   = (const float*)d_in[2];
    const float* in_proj_w = (const float*)d_in[3];
    const float* conv_w    = (const float*)d_in[4];
    const float* conv_b    = (const float*)d_in[5];
    const float* x_proj_w  = (const float*)d_in[6];
    const float* dt_proj_w = (const float*)d_in[7];
    const float* dt_proj_b = (const float*)d_in[8];
    const float* A_log     = (const float*)d_in[9];
    const float* Dvec      = (const float*)d_in[10];
    const float* out_proj_w= (const float*)d_in[11];
    const float* norm2_w   = (const float*)d_in[12];
    const float* norm2_b   = (const float*)d_in[13];
    const float* cw1       = (const float*)d_in[14];
    const float* cb1       = (const float*)d_in[15];
    const float* cw2       = (const float*)d_in[16];
    const float* cb2       = (const float*)d_in[17];
    float* out = (float*)d_out;

    void* sp = nullptr;
    cudaGetSymbolAddress(&sp, SCRATCH);
    float* S = (float*)sp;
    float* s_xn   = S + O_XN;
    float* s_xz   = S + O_XZ;
    float* s_xc   = S + O_XC;
    float* s_xdbl = S + O_XDBL;
    float* s_dt   = S + O_DT;
    float* s_y    = S + O_Y;
    float* s_x1   = S + O_X1;
    float* s_xn2  = S + O_XN2;
    float* s_fr   = S + O_FR;
    float* s_fi   = S + O_FI;

    static int attr_done = 0;
    if (!attr_done) {
        cudaFuncSetAttribute(fft_fwd_kernel,
                             cudaFuncAttributeMaxDynamicSharedMemorySize, FFT_SMEM);
        cudaFuncSetAttribute(fft_inv_kernel,
                             cudaFuncAttributeMaxDynamicSharedMemorySize, FFT_SMEM);
        attr_done = 1;
    }

    // 1) LN1
    ln_kernel<<<NTOK / 8, 256>>>(x, norm1_w, norm1_b, s_xn);
    // 2) in_proj: (4096,256) x (1024,256)^T
    gemm_tf32<<<dim3((2 * DI) / GBN, NTOK / GBM), 256>>>(s_xn, in_proj_w, nullptr,
                                                         s_xz, NTOK, 2 * DI, DIMC);
    // 3) conv + silu
    conv_silu_kernel<<<(NTOK * DI) / 256, 256>>>(s_xz, conv_w, conv_b, s_xc);
    // 4) x_proj: (4096,512) x (144,512)^T
    gemm_tf32<<<dim3((XDBLW + GBN - 1) / GBN, NTOK / GBM), 256>>>(s_xc, x_proj_w, nullptr,
                                                                  s_xdbl, NTOK, XDBLW, DI);
    // 5) dt
    dt_kernel<<<(NTOK * DI) / 256, 256>>>(s_xdbl, dt_proj_w, dt_proj_b, s_dt);
    // 6) selective scan (fused D-skip + silu(z) gate)
    scan_kernel<<<BATCH * (DI / 8), 256>>>(s_xdbl, s_dt, s_xc, s_xz, A_log, Dvec, s_y);
    // 7) out_proj + residual
    gemm_tf32<<<dim3(DIMC / GBN, NTOK / GBM), 256>>>(s_y, out_proj_w, x,
                                                     s_x1, NTOK, DIMC, DI);
    // 8) LN2
    ln_kernel<<<NTOK / 8, 256>>>(s_x1, norm2_w, norm2_b, s_xn2);
    // 9) forward 2048-pt FFT (real input, DIF), coalesced 8 ch/block
    fft_fwd_kernel<<<64, 512, FFT_SMEM>>>(s_xn2, s_fr, s_fi);
    // 10) fused EinFFT: DFT4 -> relu layer -> softshrink layer -> IDFT4
    einfft_mlp_kernel<<<NTOK / 8, 256>>>(s_fr, s_fi, cw1, cb1, cw2, cb2);
    // 11) inverse 2048-pt FFT (DIT) + real part + residual -> out
    fft_inv_kernel<<<64, 512, FFT_SMEM>>>(s_fr, s_fi, s_x1, out);
}

// round 4
// speedup vs baseline: 4.2994x; 1.8386x over previous
#include <cuda_runtime.h>
#include <math.h>

// ---------------------------------------------------------------------------
// Problem constants
// ---------------------------------------------------------------------------
#define BATCH   2
#define LSEQ    2048
#define DIMC    256
#define DI      512          // d_inner
#define DS      64           // d_state
#define DTR     16           // dt_rank
#define XDBLW   144          // dt_rank + 2*d_state
#define NTOK    (BATCH*LSEQ) // 4096
#define SQRT_INV_8192 0.011048543456039806f
#define LAMBDA_SS 0.01f
#define PI_F 3.14159265358979323846f

// ---------------------------------------------------------------------------
// Scratch (single __device__ array; no allocations anywhere)
// ---------------------------------------------------------------------------
#define O_XN    ((size_t)0)
#define O_XZ    (O_XN   + (size_t)NTOK*DIMC)
#define O_XC    (O_XZ   + (size_t)NTOK*2*DI)
#define O_XDBL  (O_XC   + (size_t)NTOK*DI)
#define O_Y     (O_XDBL + (size_t)NTOK*XDBLW)
#define O_X1    (O_Y    + (size_t)NTOK*DI)
#define O_XN2   (O_X1   + (size_t)NTOK*DIMC)
#define O_FR    (O_XN2  + (size_t)NTOK*DIMC)
#define O_FI    (O_FR   + (size_t)NTOK*DIMC)
#define O_END   (O_FI   + (size_t)NTOK*DIMC)

__device__ float SCRATCH[O_END];

// ---------------------------------------------------------------------------
// LayerNorm: one warp per token (256 channels), 8 tokens per 256-thread block
// ---------------------------------------------------------------------------
__global__ void ln_kernel(const float* __restrict__ x,
                          const float* __restrict__ w,
                          const float* __restrict__ b,
                          float* __restrict__ out) {
    int t = blockIdx.x * 8 + (threadIdx.x >> 5);
    int lane = threadIdx.x & 31;
    const float4* row = (const float4*)(x + (size_t)t * DIMC);
    float4 v0 = row[lane];
    float4 v1 = row[lane + 32];
    float s = v0.x + v0.y + v0.z + v0.w + v1.x + v1.y + v1.z + v1.w;
    #pragma unroll
    for (int off = 16; off; off >>= 1) s += __shfl_xor_sync(0xffffffffu, s, off);
    float m = s * (1.0f / 256.0f);
    float d0 = v0.x - m, d1 = v0.y - m, d2 = v0.z - m, d3 = v0.w - m;
    float d4 = v1.x - m, d5 = v1.y - m, d6 = v1.z - m, d7 = v1.w - m;
    float q = d0*d0 + d1*d1 + d2*d2 + d3*d3 + d4*d4 + d5*d5 + d6*d6 + d7*d7;
    #pragma unroll
    for (int off = 16; off; off >>= 1) q += __shfl_xor_sync(0xffffffffu, q, off);
    float inv = rsqrtf(q * (1.0f / 256.0f) + 1e-5f);
    const float4* w4 = (const float4*)w;
    const float4* b4 = (const float4*)b;
    float4* o4 = (float4*)(out + (size_t)t * DIMC);
    float4 wa = w4[lane], ba = b4[lane];
    float4 wb = w4[lane + 32], bb = b4[lane + 32];
    float4 r0, r1;
    r0.x = d0*inv*wa.x + ba.x; r0.y = d1*inv*wa.y + ba.y;
    r0.z = d2*inv*wa.z + ba.z; r0.w = d3*inv*wa.w + ba.w;
    r1.x = d4*inv*wb.x + bb.x; r1.y = d5*inv*wb.y + bb.y;
    r1.z = d6*inv*wb.z + bb.z; r1.w = d7*inv*wb.w + bb.w;
    o4[lane] = r0; o4[lane + 32] = r1;
}

// ---------------------------------------------------------------------------
// tf32 tensor-core GEMM: C[M,N] = A[M,K] * W[N,K]^T (+ R[M,N]).
// 128x64 block tile, BK=16, 256 threads = 8 warps (4m x 2n), warp tile 32x32
// via 2x4 mma.sync.m16n8k8.tf32.  Double-buffered smem.
// ---------------------------------------------------------------------------
#define GBM 128
#define GBN 64
#define ASTR 20

__device__ __forceinline__ unsigned f2tf(float x) {
    unsigned r;
    asm("cvt.rna.tf32.f32 %0, %1;" : "=r"(r) : "f"(x));
    return r;
}
__device__ __forceinline__ float4 cvt4(float4 v) {
    float4 o;
    o.x = __uint_as_float(f2tf(v.x));
    o.y = __uint_as_float(f2tf(v.y));
    o.z = __uint_as_float(f2tf(v.z));
    o.w = __uint_as_float(f2tf(v.w));
    return o;
}
__device__ __forceinline__ void mma_tf32(float* c, const unsigned* a, const unsigned* b) {
    asm volatile(
        "mma.sync.aligned.m16n8k8.row.col.f32.tf32.tf32.f32 "
        "{%0,%1,%2,%3}, {%4,%5,%6,%7}, {%8,%9}, {%0,%1,%2,%3};"
        : "+f"(c[0]), "+f"(c[1]), "+f"(c[2]), "+f"(c[3])
        : "r"(a[0]), "r"(a[1]), "r"(a[2]), "r"(a[3]), "r"(b[0]), "r"(b[1]));
}

__global__ void __launch_bounds__(256) gemm_tf32(const float* __restrict__ A,
                                                 const float* __restrict__ W,
                                                 const float* __restrict__ R,
                                                 float* __restrict__ C,
                                                 int M, int N, int K) {
    __shared__ float As[2][GBM * ASTR];
    __shared__ float Bs[2][GBN * ASTR];
    int m0 = blockIdx.y * GBM;
    int n0 = blockIdx.x * GBN;
    int tid = threadIdx.x;
    int wid = tid >> 5, lane = tid & 31;
    int wm = (wid & 3) * 32;
    int wn = (wid >> 2) * 32;
    int gid = lane >> 2;       // 0..7
    int tig = lane & 3;        // 0..3
    int ar = tid >> 1, ak = (tid & 1) * 8;
    int br = tid >> 2, bk = (tid & 3) * 4;

    float acc[2][4][4];
    #pragma unroll
    for (int mi = 0; mi < 2; mi++)
        #pragma unroll
        for (int ni = 0; ni < 4; ni++)
            #pragma unroll
            for (int q = 0; q < 4; q++) acc[mi][ni][q] = 0.0f;

    float4 a4a, a4b, b4;
    a4a = *(const float4*)(A + (size_t)(m0 + ar) * K + ak);
    a4b = *(const float4*)(A + (size_t)(m0 + ar) * K + ak + 4);
    b4 = (n0 + br < N) ? *(const float4*)(W + (size_t)(n0 + br) * K + bk)
                       : make_float4(0.f, 0.f, 0.f, 0.f);
    *(float4*)(&As[0][ar * ASTR + ak])     = cvt4(a4a);
    *(float4*)(&As[0][ar * ASTR + ak + 4]) = cvt4(a4b);
    *(float4*)(&Bs[0][br * ASTR + bk])     = cvt4(b4);
    __syncthreads();

    int nIt = K >> 4;
    for (int it = 0; it < nIt; it++) {
        int buf = it & 1;
        if (it + 1 < nIt) {
            int k0 = (it + 1) << 4;
            a4a = *(const float4*)(A + (size_t)(m0 + ar) * K + k0 + ak);
            a4b = *(const float4*)(A + (size_t)(m0 + ar) * K + k0 + ak + 4);
            b4 = (n0 + br < N) ? *(const float4*)(W + (size_t)(n0 + br) * K + k0 + bk)
                               : make_float4(0.f, 0.f, 0.f, 0.f);
        }
        #pragma unroll
        for (int ks = 0; ks < 2; ks++) {
            int k8 = ks * 8;
            unsigned afr[2][4], bfr[4][2];
            #pragma unroll
            for (int mi = 0; mi < 2; mi++) {
                int rb = wm + mi * 16 + gid;
                afr[mi][0] = __float_as_uint(As[buf][(rb)     * ASTR + k8 + tig]);
                afr[mi][1] = __float_as_uint(As[buf][(rb + 8) * ASTR + k8 + tig]);
                afr[mi][2] = __float_as_uint(As[buf][(rb)     * ASTR + k8 + tig + 4]);
                afr[mi][3] = __float_as_uint(As[buf][(rb + 8) * ASTR + k8 + tig + 4]);
            }
            #pragma unroll
            for (int ni = 0; ni < 4; ni++) {
                int cb = wn + ni * 8 + gid;
                bfr[ni][0] = __float_as_uint(Bs[buf][cb * ASTR + k8 + tig]);
                bfr[ni][1] = __float_as_uint(Bs[buf][cb * ASTR + k8 + tig + 4]);
            }
            #pragma unroll
            for (int mi = 0; mi < 2; mi++)
                #pragma unroll
                for (int ni = 0; ni < 4; ni++)
                    mma_tf32(acc[mi][ni], afr[mi], bfr[ni]);
        }
        if (it + 1 < nIt) {
            int nb = buf ^ 1;
            *(float4*)(&As[nb][ar * ASTR + ak])     = cvt4(a4a);
            *(float4*)(&As[nb][ar * ASTR + ak + 4]) = cvt4(a4b);
            *(float4*)(&Bs[nb][br * ASTR + bk])     = cvt4(b4);
        }
        __syncthreads();
    }

    #pragma unroll
    for (int mi = 0; mi < 2; mi++) {
        int row = m0 + wm + mi * 16 + gid;
        #pragma unroll
        for (int ni = 0; ni < 4; ni++) {
            int col = n0 + wn + ni * 8 + tig * 2;
            if (col < N) {
                float v0 = acc[mi][ni][0];
                float v2 = acc[mi][ni][2];
                if (R) { v0 += R[(size_t)row * N + col]; v2 += R[(size_t)(row + 8) * N + col]; }
                C[(size_t)row * N + col] = v0;
                C[(size_t)(row + 8) * N + col] = v2;
            }
            if (col + 1 < N) {
                float v1 = acc[mi][ni][1];
                float v3 = acc[mi][ni][3];
                if (R) { v1 += R[(size_t)row * N + col + 1]; v3 += R[(size_t)(row + 8) * N + col + 1]; }
                C[(size_t)row * N + col + 1] = v1;
                C[(size_t)(row + 8) * N + col + 1] = v3;
            }
        }
    }
}

// ---------------------------------------------------------------------------
// Depthwise causal conv (k=4) + bias + SiLU.  xz[:, 0:512] -> xc
// ---------------------------------------------------------------------------
__global__ void conv_silu_kernel(const float* __restrict__ xz,
                                 const float* __restrict__ cw,
                                 const float* __restrict__ cb,
                                 float* __restrict__ xc) {
    int idx = blockIdx.x * 256 + threadIdx.x;   // NTOK*DI
    int d = idx & (DI - 1);
    int bt = idx >> 9;
    int b = bt >> 11;
    int l = bt & (LSEQ - 1);
    float acc = cb[d];
    #pragma unroll
    for (int k = 0; k < 4; k++) {
        int ls = l + k - 3;
        if (ls >= 0)
            acc += xz[((size_t)((b << 11) | ls)) * (2 * DI) + d] * cw[d * 4 + k];
    }
    float sg = 1.0f / (1.0f + __expf(-acc));
    xc[(size_t)bt * DI + d] = acc * sg;
}

// ---------------------------------------------------------------------------
// Selective scan with fused dt (softplus(x16 @ dtw^T + b)).
// One warp per (b, d) channel; lane owns states s, s+32.
// y reduction deferred: 32 per-step partials in registers, then one
// recursive-halving reduce-scatter (31 shfls / 32 steps); lane j ends with
// y(t0+j) and applies D-skip + silu(z) gate itself.
// ---------------------------------------------------------------------------
#define TCHUNK 64
__global__ void __launch_bounds__(256) scan_kernel(
        const float* __restrict__ xdbl,
        const float* __restrict__ xc,
        const float* __restrict__ xz,
        const float* __restrict__ A_log,
        const float* __restrict__ Dvec,
        const float* __restrict__ dtw,
        const float* __restrict__ dtb,
        float* __restrict__ y) {
    __shared__ float sB[TCHUNK][64];
    __shared__ float sC[TCHUNK][64];
    __shared__ float sx16[TCHUNK][16];
    __shared__ float2 sdx[TCHUNK][8];   // (dt, xc)
    __shared__ float sz[TCHUNK][8];
    __shared__ float sy[TCHUNK][8];
    __shared__ float sw[8][16];
    __shared__ float sbias[8];

    int b = blockIdx.x >> 6;
    int dbase = (blockIdx.x & 63) * 8;
    int wid = threadIdx.x >> 5;
    int lane = threadIdx.x & 31;
    int d = dbase + wid;

    if (threadIdx.x < 128) {
        int di = threadIdx.x >> 4, r = threadIdx.x & 15;
        sw[di][r] = dtw[(dbase + di) * DTR + r];
        if (r == 0) sbias[di] = dtb[dbase + di];
    }
    float A0 = -__expf(A_log[d * DS + lane]);
    float A1 = -__expf(A_log[d * DS + lane + 32]);
    float Dd = Dvec[d];
    float h0 = 0.0f, h1 = 0.0f;

    for (int t0 = 0; t0 < LSEQ; t0 += TCHUNK) {
        // stage B, C
        for (int i = threadIdx.x; i < TCHUNK * 128; i += 256) {
            int tt = i >> 7;
            int c = i & 127;
            float v = xdbl[(size_t)(b * LSEQ + t0 + tt) * XDBLW + DTR + c];
            if (c < 64) sB[tt][c] = v; else sC[tt][c - 64] = v;
        }
        // stage dt-rank inputs
        for (int i = threadIdx.x; i < TCHUNK * 16; i += 256) {
            int tt = i >> 4, r = i & 15;
            sx16[tt][r] = xdbl[(size_t)(b * LSEQ + t0 + tt) * XDBLW + r];
        }
        // stage xc, z
        for (int i = threadIdx.x; i < TCHUNK * 8; i += 256) {
            int tt = i >> 3, di = i & 7;
            size_t bt = (size_t)(b * LSEQ + t0 + tt);
            sdx[tt][di].y = xc[bt * DI + dbase + di];
            sz[tt][di]    = xz[bt * (2 * DI) + DI + dbase + di];
        }
        __syncthreads();
        // compute dt = softplus(x16 . w + b)
        for (int i = threadIdx.x; i < TCHUNK * 8; i += 256) {
            int tt = i >> 3, di = i & 7;
            float acc = sbias[di];
            #pragma unroll
            for (int r = 0; r < 16; r++) acc = fmaf(sx16[tt][r], sw[di][r], acc);
            sdx[tt][di].x = (acc > 20.0f) ? acc : __logf(1.0f + __expf(acc));
        }
        __syncthreads();

        #pragma unroll 1
        for (int g = 0; g < TCHUNK / 32; g++) {
            float part[32];
            #pragma unroll
            for (int j = 0; j < 32; j++) {
                int tt = g * 32 + j;
                float2 dx = sdx[tt][wid];
                float du = dx.x * dx.y;
                float dA0 = __expf(dx.x * A0);
                float dA1 = __expf(dx.x * A1);
                h0 = fmaf(dA0, h0, du * sB[tt][lane]);
                h1 = fmaf(dA1, h1, du * sB[tt][lane + 32]);
                part[j] = fmaf(h0, sC[tt][lane], h1 * sC[tt][lane + 32]);
            }
            // recursive-halving reduce-scatter: lane j gets sum for step g*32+j
            #pragma unroll
            for (int s = 16; s >= 1; s >>= 1) {
                bool up = (lane & s) != 0;
                #pragma unroll
                for (int i2 = 0; i2 < 16; i2++) {
                    if (i2 >= s) break;
                    float keep = up ? part[i2 + s] : part[i2];
                    float send = up ? part[i2] : part[i2 + s];
                    part[i2] = keep + __shfl_xor_sync(0xffffffffu, send, s);
                }
            }
            int tt = g * 32 + lane;
            float2 dx = sdx[tt][wid];
            float zv = sz[tt][wid];
            float gate = zv / (1.0f + __expf(-zv));
            sy[tt][wid] = fmaf(dx.y, Dd, part[0]) * gate;
        }
        __syncthreads();
        for (int i = threadIdx.x; i < TCHUNK * 8; i += 256) {
            int tt = i >> 3, di = i & 7;
            y[(size_t)(b * LSEQ + t0 + tt) * DI + dbase + di] = sy[tt][di];
        }
        __syncthreads();
    }
}

// ---------------------------------------------------------------------------
// Forward 2048-pt FFT (DIF, natural -> bit-reversed), real input.
// 8 channels per block (coalesced global I/O), padded smem stride 2049.
// ---------------------------------------------------------------------------
#define FSTR 2049
#define FFT_SMEM (2 * 8 * FSTR * 4)

__global__ void __launch_bounds__(512) fft_fwd_kernel(const float* __restrict__ xin,
                                                      float* __restrict__ dR,
                                                      float* __restrict__ dI) {
    extern __shared__ float sm[];
    float* sr = sm;
    float* si = sm + 8 * FSTR;
    int b = blockIdx.x >> 5;
    int c0 = (blockIdx.x & 31) * 8;
    size_t base = (size_t)b * LSEQ * DIMC + c0;
    int tid = threadIdx.x;

    for (int t = tid; t < 8 * 2048; t += 512) {
        int n = t >> 3, j = t & 7;
        sr[j * FSTR + n] = xin[base + (size_t)n * DIMC + j];
        si[j * FSTR + n] = 0.0f;
    }
    __syncthreads();

    #pragma unroll
    for (int hb = 10; hb >= 0; hb--) {
        int half = 1 << hb;
        float th = -PI_F / (float)half;
        for (int e = tid; e < 8192; e += 512) {
            int col = e >> 10, idx = e & 1023;
            int j = idx & (half - 1);
            int pos = ((idx >> hb) << (hb + 1)) + j;
            float* cr = sr + col * FSTR;
            float* ci = si + col * FSTR;
            float ar = cr[pos],        ai = ci[pos];
            float br = cr[pos + half], bi = ci[pos + half];
            float wi, wr;
            __sincosf(th * (float)j, &wi, &wr);
            float xr = ar - br, xi = ai - bi;
            cr[pos] = ar + br;  ci[pos] = ai + bi;
            cr[pos + half] = xr * wr - xi * wi;
            ci[pos + half] = xr * wi + xi * wr;
        }
        __syncthreads();
    }

    for (int t = tid; t < 8 * 2048; t += 512) {
        int n = t >> 3, j = t & 7;
        dR[base + (size_t)n * DIMC + j] = sr[j * FSTR + n];
        dI[base + (size_t)n * DIMC + j] = si[j * FSTR + n];
    }
}

// ---------------------------------------------------------------------------
// Inverse 2048-pt FFT (DIT, bit-reversed -> natural); output = real part
// + residual x1, written straight to out.
// ---------------------------------------------------------------------------
__global__ void __launch_bounds__(512) fft_inv_kernel(const float* __restrict__ dR,
                                                      const float* __restrict__ dI,
                                                      const float* __restrict__ x1,
                                                      float* __restrict__ out) {
    extern __shared__ float sm[];
    float* sr = sm;
    float* si = sm + 8 * FSTR;
    int b = blockIdx.x >> 5;
    int c0 = (blockIdx.x & 31) * 8;
    size_t base = (size_t)b * LSEQ * DIMC + c0;
    int tid = threadIdx.x;

    for (int t = tid; t < 8 * 2048; t += 512) {
        int n = t >> 3, j = t & 7;
        sr[j * FSTR + n] = dR[base + (size_t)n * DIMC + j];
        si[j * FSTR + n] = dI[base + (size_t)n * DIMC + j];
    }
    __syncthreads();

    #pragma unroll
    for (int hb = 0; hb <= 10; hb++) {
        int half = 1 << hb;
        float th = PI_F / (float)half;
        for (int e = tid; e < 8192; e += 512) {
            int col = e >> 10, idx = e & 1023;
            int j = idx & (half - 1);
            int pos = ((idx >> hb) << (hb + 1)) + j;
            float* cr = sr + col * FSTR;
            float* ci = si + col * FSTR;
            float ar = cr[pos],        ai = ci[pos];
            float br = cr[pos + half], bi = ci[pos + half];
            float wi, wr;
            __sincosf(th * (float)j, &wi, &wr);
            float tr = br * wr - bi * wi;
            float ti = br * wi + bi * wr;
            cr[pos] = ar + tr;         ci[pos] = ai + ti;
            cr[pos + half] = ar - tr;  ci[pos + half] = ai - ti;
        }
        __syncthreads();
    }

    for (int t = tid; t < 8 * 2048; t += 512) {
        int n = t >> 3, j = t & 7;
        size_t a = base + (size_t)n * DIMC + j;
        out[a] = x1[a] + sr[j * FSTR + n];
    }
}

// ---------------------------------------------------------------------------
// EinFFT MLP with DFT4/IDFT4 over the NB axis folded in.
// ---------------------------------------------------------------------------
__global__ void __launch_bounds__(256) einfft_mlp_kernel(
        float* __restrict__ fR, float* __restrict__ fI,
        const float* __restrict__ cw1, const float* __restrict__ cb1,
        const float* __restrict__ cw2, const float* __restrict__ cb2) {
    __shared__ float sR[2048], sI[2048];
    __shared__ float tR[2048], tI[2048];
    int row0 = blockIdx.x * 8;
    int tid = threadIdx.x;
    for (int i = tid; i < 2048; i += 256) {
        sR[i] = fR[(size_t)row0 * DIMC + i];
        sI[i] = fI[(size_t)row0 * DIMC + i];
    }
    __syncthreads();

    const float sc = SQRT_INV_8192;
    #pragma unroll
    for (int g = tid; g < 512; g += 256) {
        int r = g >> 6, s = g & 63;
        int p = r * 256 + s;
        float r0 = sR[p],       i0 = sI[p];
        float r1 = sR[p + 64],  i1 = sI[p + 64];
        float r2 = sR[p + 128], i2 = sI[p + 128];
        float r3 = sR[p + 192], i3 = sI[p + 192];
        sR[p]       = (r0 + r1 + r2 + r3) * sc;
        sI[p]       = (i0 + i1 + i2 + i3) * sc;
        sR[p + 64]  = (r0 + i1 - r2 - i3) * sc;
        sI[p + 64]  = (i0 - r1 - i2 + r3) * sc;
        sR[p + 128] = (r0 - r1 + r2 - r3) * sc;
        sI[p + 128] = (i0 - i1 + i2 - i3) * sc;
        sR[p + 192] = (r0 - i1 - r2 + i3) * sc;
        sI[p + 192] = (i0 + r1 - i2 - r3) * sc;
    }
    __syncthreads();

    int k = tid >> 6, o = tid & 63;

    {
        const float* w0 = cw1 + k * 4096;
        const float* w1 = cw1 + 16384 + k * 4096;
        float bR = cb1[k * 64 + o];
        float bI = cb1[256 + k * 64 + o];
        float aR[8], aI[8];
        #pragma unroll
        for (int r = 0; r < 8; r++) { aR[r] = bR; aI[r] = bI; }
        for (int dd = 0; dd < 64; dd++) {
            float wa = w0[dd * 64 + o];
            float wb = w1[dd * 64 + o];
            int sb = k * 64 + dd;
            #pragma unroll
            for (int r = 0; r < 8; r++) {
                float xr = sR[r * 256 + sb];
                float xi = sI[r * 256 + sb];
                aR[r] = fmaf(xr, wa, fmaf(-xi, wb, aR[r]));
                aI[r] = fmaf(xr, wb, fmaf( xi, wa, aI[r]));
            }
        }
        #pragma unroll
        for (int r = 0; r < 8; r++) {
            tR[r * 256 + tid] = fmaxf(aR[r], 0.0f);
            tI[r * 256 + tid] = fmaxf(aI[r], 0.0f);
        }
    }
    __syncthreads();

    {
        const float* w0 = cw2 + k * 4096;
        const float* w1 = cw2 + 16384 + k * 4096;
        float bR = cb2[k * 64 + o];
        float bI = cb2[256 + k * 64 + o];
        float aR[8], aI[8];
        #pragma unroll
        for (int r = 0; r < 8; r++) { aR[r] = bR; aI[r] = bI; }
        for (int dd = 0; dd < 64; dd++) {
            float wa = w0[dd * 64 + o];
            float wb = w1[dd * 64 + o];
            int sb = k * 64 + dd;
            #pragma unroll
            for (int r = 0; r < 8; r++) {
                float xr = tR[r * 256 + sb];
                float xi = tI[r * 256 + sb];
                aR[r] = fmaf(xr, wa, fmaf(-xi, wb, aR[r]));
                aI[r] = fmaf(xr, wb, fmaf( xi, wa, aI[r]));
            }
        }
        #pragma unroll
        for (int r = 0; r < 8; r++) {
            float vR = aR[r], vI = aI[r];
            vR = (vR > LAMBDA_SS) ? vR - LAMBDA_SS
                 : ((vR < -LAMBDA_SS) ? vR + LAMBDA_SS : 0.0f);
            vI = (vI > LAMBDA_SS) ? vI - LAMBDA_SS
                 : ((vI < -LAMBDA_SS) ? vI + LAMBDA_SS : 0.0f);
            sR[r * 256 + tid] = vR;
            sI[r * 256 + tid] = vI;
        }
    }
    __syncthreads();

    #pragma unroll
    for (int g = tid; g < 512; g += 256) {
        int r = g >> 6, s = g & 63;
        int p = r * 256 + s;
        float R0 = sR[p],       I0 = sI[p];
        float R1 = sR[p + 64],  I1 = sI[p + 64];
        float R2 = sR[p + 128], I2 = sI[p + 128];
        float R3 = sR[p + 192], I3 = sI[p + 192];
        sR[p]       = (R0 + R1 + R2 + R3) * sc;
        sI[p]       = (I0 + I1 + I2 + I3) * sc;
        sR[p + 64]  = (R0 - I1 - R2 + I3) * sc;
        sI[p + 64]  = (I0 + R1 - I2 - R3) * sc;
        sR[p + 128] = (R0 - R1 + R2 - R3) * sc;
        sI[p + 128] = (I0 - I1 + I2 - I3) * sc;
        sR[p + 192] = (R0 + I1 - R2 - I3) * sc;
        sI[p + 192] = (I0 - R1 - I2 + R3) * sc;
    }
    __syncthreads();

    for (int i = tid; i < 2048; i += 256) {
        fR[(size_t)row0 * DIMC + i] = sR[i];
        fI[(size_t)row0 * DIMC + i] = sI[i];
    }
}

// ---------------------------------------------------------------------------
// Launch
// ---------------------------------------------------------------------------
extern "C" void kernel_launch(void* const* d_in, const int* in_sizes, int n_in,
                              void* d_out, int out_size) {
    const float* x         = (const float*)d_in[0];
    const float* norm1_w   = (const float*)d_in[1];
    const float* norm1_b   = (const float*)d_in[2];
    const float* in_proj_w = (const float*)d_in[3];
    const float* conv_w    = (const float*)d_in[4];
    const float* conv_b    = (const float*)d_in[5];
    const float* x_proj_w  = (const float*)d_in[6];
    const float* dt_proj_w = (const float*)d_in[7];
    const float* dt_proj_b = (const float*)d_in[8];
    const float* A_log     = (const float*)d_in[9];
    const float* Dvec      = (const float*)d_in[10];
    const float* out_proj_w= (const float*)d_in[11];
    const float* norm2_w   = (const float*)d_in[12];
    const float* norm2_b   = (const float*)d_in[13];
    const float* cw1       = (const float*)d_in[14];
    const float* cb1       = (const float*)d_in[15];
    const float* cw2       = (const float*)d_in[16];
    const float* cb2       = (const float*)d_in[17];
    float* out = (float*)d_out;

    void* sp = nullptr;
    cudaGetSymbolAddress(&sp, SCRATCH);
    float* S = (float*)sp;
    float* s_xn   = S + O_XN;
    float* s_xz   = S + O_XZ;
    float* s_xc   = S + O_XC;
    float* s_xdbl = S + O_XDBL;
    float* s_y    = S + O_Y;
    float* s_x1   = S + O_X1;
    float* s_xn2  = S + O_XN2;
    float* s_fr   = S + O_FR;
    float* s_fi   = S + O_FI;

    static int attr_done = 0;
    if (!attr_done) {
        cudaFuncSetAttribute(fft_fwd_kernel,
                             cudaFuncAttributeMaxDynamicSharedMemorySize, FFT_SMEM);
        cudaFuncSetAttribute(fft_inv_kernel,
                             cudaFuncAttributeMaxDynamicSharedMemorySize, FFT_SMEM);
        attr_done = 1;
    }

    // 1) LN1
    ln_kernel<<<NTOK / 8, 256>>>(x, norm1_w, norm1_b, s_xn);
    // 2) in_proj
    gemm_tf32<<<dim3((2 * DI) / GBN, NTOK / GBM), 256>>>(s_xn, in_proj_w, nullptr,
                                                         s_xz, NTOK, 2 * DI, DIMC);
    // 3) conv + silu
    conv_silu_kernel<<<(NTOK * DI) / 256, 256>>>(s_xz, conv_w, conv_b, s_xc);
    // 4) x_proj
    gemm_tf32<<<dim3((XDBLW + GBN - 1) / GBN, NTOK / GBM), 256>>>(s_xc, x_proj_w, nullptr,
                                                                  s_xdbl, NTOK, XDBLW, DI);
    // 5) selective scan (fused dt + D-skip + silu(z) gate)
    scan_kernel<<<BATCH * (DI / 8), 256>>>(s_xdbl, s_xc, s_xz, A_log, Dvec,
                                           dt_proj_w, dt_proj_b, s_y);
    // 6) out_proj + residual
    gemm_tf32<<<dim3(DIMC / GBN, NTOK / GBM), 256>>>(s_y, out_proj_w, x,
                                                     s_x1, NTOK, DIMC, DI);
    // 7) LN2
    ln_kernel<<<NTOK / 8, 256>>>(s_x1, norm2_w, norm2_b, s_xn2);
    // 8) forward FFT
    fft_fwd_kernel<<<64, 512, FFT_SMEM>>>(s_xn2, s_fr, s_fi);
    // 9) fused EinFFT MLP (DFT4 + relu + softshrink + IDFT4)
    einfft_mlp_kernel<<<NTOK / 8, 256>>>(s_fr, s_fi, cw1, cb1, cw2, cb2);
    // 10) inverse FFT + residual -> out
    fft_inv_kernel<<<64, 512, FFT_SMEM>>>(s_fr, s_fi, s_x1, out);
}

// round 6
// speedup vs baseline: 4.7560x; 1.1062x over previous
#include <cuda_runtime.h>
#include <stdint.h>
#include <math.h>

// ---------------------------------------------------------------------------
// Problem constants
// ---------------------------------------------------------------------------
#define BATCH   2
#define LSEQ    2048
#define DIMC    256
#define DI      512          // d_inner
#define DS      64           // d_state
#define DTR     16           // dt_rank
#define XDBLW   144          // dt_rank + 2*d_state
#define NTOK    (BATCH*LSEQ) // 4096
#define SQRT_INV_8192 0.011048543456039806f
#define LAMBDA_SS 0.01f
#define PI_F 3.14159265358979323846f

// ---------------------------------------------------------------------------
// Scratch (single __device__ array; no allocations anywhere)
// ---------------------------------------------------------------------------
#define O_XN    ((size_t)0)
#define O_XZ    (O_XN   + (size_t)NTOK*DIMC)
#define O_XC    (O_XZ   + (size_t)NTOK*2*DI)
#define O_XDBL  (O_XC   + (size_t)NTOK*DI)
#define O_Y     (O_XDBL + (size_t)NTOK*XDBLW)
#define O_X1    (O_Y    + (size_t)NTOK*DI)
#define O_XN2   (O_X1   + (size_t)NTOK*DIMC)
#define O_FR    (O_XN2  + (size_t)NTOK*DIMC)
#define O_FI    (O_FR   + (size_t)NTOK*DIMC)
#define O_END   (O_FI   + (size_t)NTOK*DIMC)

__device__ float SCRATCH[O_END];

// ---------------------------------------------------------------------------
// cp.async helpers
// ---------------------------------------------------------------------------
__device__ __forceinline__ void cp16(unsigned dst, const void* src, int sz) {
    asm volatile("cp.async.cg.shared.global [%0], [%1], 16, %2;"
                 :: "r"(dst), "l"(src), "r"(sz));
}
__device__ __forceinline__ void cp_commit() {
    asm volatile("cp.async.commit_group;" ::: "memory");
}
template <int N>
__device__ __forceinline__ void cp_wait() {
    asm volatile("cp.async.wait_group %0;" :: "n"(N) : "memory");
}

// ---------------------------------------------------------------------------
// LayerNorm: one warp per token (256 channels), 8 tokens per 256-thread block
// ---------------------------------------------------------------------------
__global__ void ln_kernel(const float* __restrict__ x,
                          const float* __restrict__ w,
                          const float* __restrict__ b,
                          float* __restrict__ out) {
    int t = blockIdx.x * 8 + (threadIdx.x >> 5);
    int lane = threadIdx.x & 31;
    const float4* row = (const float4*)(x + (size_t)t * DIMC);
    float4 v0 = row[lane];
    float4 v1 = row[lane + 32];
    float s = v0.x + v0.y + v0.z + v0.w + v1.x + v1.y + v1.z + v1.w;
    #pragma unroll
    for (int off = 16; off; off >>= 1) s += __shfl_xor_sync(0xffffffffu, s, off);
    float m = s * (1.0f / 256.0f);
    float d0 = v0.x - m, d1 = v0.y - m, d2 = v0.z - m, d3 = v0.w - m;
    float d4 = v1.x - m, d5 = v1.y - m, d6 = v1.z - m, d7 = v1.w - m;
    float q = d0*d0 + d1*d1 + d2*d2 + d3*d3 + d4*d4 + d5*d5 + d6*d6 + d7*d7;
    #pragma unroll
    for (int off = 16; off; off >>= 1) q += __shfl_xor_sync(0xffffffffu, q, off);
    float inv = rsqrtf(q * (1.0f / 256.0f) + 1e-5f);
    const float4* w4 = (const float4*)w;
    const float4* b4 = (const float4*)b;
    float4* o4 = (float4*)(out + (size_t)t * DIMC);
    float4 wa = w4[lane], ba = b4[lane];
    float4 wb = w4[lane + 32], bb = b4[lane + 32];
    float4 r0, r1;
    r0.x = d0*inv*wa.x + ba.x; r0.y = d1*inv*wa.y + ba.y;
    r0.z = d2*inv*wa.z + ba.z; r0.w = d3*inv*wa.w + ba.w;
    r1.x = d4*inv*wb.x + bb.x; r1.y = d5*inv*wb.y + bb.y;
    r1.z = d6*inv*wb.z + bb.z; r1.w = d7*inv*wb.w + bb.w;
    o4[lane] = r0; o4[lane + 32] = r1;
}

// ---------------------------------------------------------------------------
// tf32 tensor-core GEMM: C[M,N] = A[M,K] * W[N,K]^T (+ R[M,N]).
// 128x64 block tile, BK=16, 8 warps (4m x 2n), warp tile 32x32 via 2x4
// mma.sync.m16n8k8.tf32.  4-stage cp.async pipeline; raw fp32 bits fed to
// HMMA (hardware truncates to tf32).  M%128==0, K%16==0 guaranteed.
// ---------------------------------------------------------------------------
#define GBM 128
#define GBN 64
#define ASTR 20
#define GSTAGES 4
#define GEMM_SMEM (GSTAGES * (GBM + GBN) * ASTR * 4)

__device__ __forceinline__ void mma_tf32(float* c, const unsigned* a, const unsigned* b) {
    asm volatile(
        "mma.sync.aligned.m16n8k8.row.col.f32.tf32.tf32.f32 "
        "{%0,%1,%2,%3}, {%4,%5,%6,%7}, {%8,%9}, {%0,%1,%2,%3};"
        : "+f"(c[0]), "+f"(c[1]), "+f"(c[2]), "+f"(c[3])
        : "r"(a[0]), "r"(a[1]), "r"(a[2]), "r"(a[3]), "r"(b[0]), "r"(b[1]));
}

__global__ void __launch_bounds__(256) gemm_tf32(const float* __restrict__ A,
                                                 const float* __restrict__ W,
                                                 const float* __restrict__ R,
                                                 float* __restrict__ C,
                                                 int M, int N, int K) {
    extern __shared__ float gsm[];
    float* As = gsm;                                // GSTAGES * GBM * ASTR
    float* Bs = gsm + GSTAGES * GBM * ASTR;         // GSTAGES * GBN * ASTR
    unsigned smA = (unsigned)__cvta_generic_to_shared(As);
    unsigned smB = (unsigned)__cvta_generic_to_shared(Bs);

    int m0 = blockIdx.y * GBM;
    int n0 = blockIdx.x * GBN;
    int tid = threadIdx.x;
    int wid = tid >> 5, lane = tid & 31;
    int wm = (wid & 3) * 32;
    int wn = (wid >> 2) * 32;
    int gid = lane >> 2;       // 0..7
    int tig = lane & 3;        // 0..3
    int ar = tid >> 1, ak = (tid & 1) * 8;
    int br = tid >> 2, bk = (tid & 3) * 4;

    const float* Abase = A + (size_t)(m0 + ar) * K + ak;
    bool bok = (n0 + br) < N;
    const float* Bbase = bok ? (W + (size_t)(n0 + br) * K + bk) : W;
    int bsz = bok ? 16 : 0;
    unsigned adst = smA + (unsigned)(ar * ASTR + ak) * 4u;
    unsigned bdst = smB + (unsigned)(br * ASTR + bk) * 4u;
    const unsigned aStage = GBM * ASTR * 4u;
    const unsigned bStage = GBN * ASTR * 4u;

    float acc[2][4][4];
    #pragma unroll
    for (int mi = 0; mi < 2; mi++)
        #pragma unroll
        for (int ni = 0; ni < 4; ni++)
            #pragma unroll
            for (int q = 0; q < 4; q++) acc[mi][ni][q] = 0.0f;

    int nIt = K >> 4;
    // prologue: stages 0..GSTAGES-2
    #pragma unroll
    for (int s = 0; s < GSTAGES - 1; s++) {
        cp16(adst + s * aStage,      Abase + s * 16,     16);
        cp16(adst + s * aStage + 16, Abase + s * 16 + 4, 16);
        cp16(bdst + s * bStage,      Bbase + (bok ? s * 16 : 0), bsz);
        cp_commit();
    }

    for (int it = 0; it < nIt; it++) {
        cp_wait<GSTAGES - 2>();
        __syncthreads();
        int buf = it & (GSTAGES - 1);
        const float* Ab = As + buf * (GBM * ASTR);
        const float* Bb = Bs + buf * (GBN * ASTR);
        #pragma unroll
        for (int ks = 0; ks < 2; ks++) {
            int k8 = ks * 8;
            unsigned afr[2][4], bfr[4][2];
            #pragma unroll
            for (int mi = 0; mi < 2; mi++) {
                int rb = wm + mi * 16 + gid;
                afr[mi][0] = __float_as_uint(Ab[(rb)     * ASTR + k8 + tig]);
                afr[mi][1] = __float_as_uint(Ab[(rb + 8) * ASTR + k8 + tig]);
                afr[mi][2] = __float_as_uint(Ab[(rb)     * ASTR + k8 + tig + 4]);
                afr[mi][3] = __float_as_uint(Ab[(rb + 8) * ASTR + k8 + tig + 4]);
            }
            #pragma unroll
            for (int ni = 0; ni < 4; ni++) {
                int cb = wn + ni * 8 + gid;
                bfr[ni][0] = __float_as_uint(Bb[cb * ASTR + k8 + tig]);
                bfr[ni][1] = __float_as_uint(Bb[cb * ASTR + k8 + tig + 4]);
            }
            #pragma unroll
            for (int mi = 0; mi < 2; mi++)
                #pragma unroll
                for (int ni = 0; ni < 4; ni++)
                    mma_tf32(acc[mi][ni], afr[mi], bfr[ni]);
        }
        int nx = it + GSTAGES - 1;
        if (nx < nIt) {
            int slot = nx & (GSTAGES - 1);
            cp16(adst + slot * aStage,      Abase + nx * 16,     16);
            cp16(adst + slot * aStage + 16, Abase + nx * 16 + 4, 16);
            cp16(bdst + slot * bStage,      Bbase + (bok ? nx * 16 : 0), bsz);
        }
        cp_commit();
    }

    #pragma unroll
    for (int mi = 0; mi < 2; mi++) {
        int row = m0 + wm + mi * 16 + gid;
        #pragma unroll
        for (int ni = 0; ni < 4; ni++) {
            int col = n0 + wn + ni * 8 + tig * 2;
            if (col < N) {
                float v0 = acc[mi][ni][0];
                float v2 = acc[mi][ni][2];
                if (R) { v0 += R[(size_t)row * N + col]; v2 += R[(size_t)(row + 8) * N + col]; }
                C[(size_t)row * N + col] = v0;
                C[(size_t)(row + 8) * N + col] = v2;
            }
            if (col + 1 < N) {
                float v1 = acc[mi][ni][1];
                float v3 = acc[mi][ni][3];
                if (R) { v1 += R[(size_t)row * N + col + 1]; v3 += R[(size_t)(row + 8) * N + col + 1]; }
                C[(size_t)row * N + col + 1] = v1;
                C[(size_t)(row + 8) * N + col + 1] = v3;
            }
        }
    }
}

// ---------------------------------------------------------------------------
// Depthwise causal conv (k=4) + bias + SiLU.  xz[:, 0:512] -> xc
// ---------------------------------------------------------------------------
__global__ void conv_silu_kernel(const float* __restrict__ xz,
                                 const float* __restrict__ cw,
                                 const float* __restrict__ cb,
                                 float* __restrict__ xc) {
    int idx = blockIdx.x * 256 + threadIdx.x;   // NTOK*DI
    int d = idx & (DI - 1);
    int bt = idx >> 9;
    int b = bt >> 11;
    int l = bt & (LSEQ - 1);
    float acc = cb[d];
    #pragma unroll
    for (int k = 0; k < 4; k++) {
        int ls = l + k - 3;
        if (ls >= 0)
            acc += xz[((size_t)((b << 11) | ls)) * (2 * DI) + d] * cw[d * 4 + k];
    }
    float sg = 1.0f / (1.0f + __expf(-acc));
    xc[(size_t)bt * DI + d] = acc * sg;
}

// ---------------------------------------------------------------------------
// Selective scan with fused dt; deferred reduce-scatter for y.
// ---------------------------------------------------------------------------
#define TCHUNK 64
__global__ void __launch_bounds__(256) scan_kernel(
        const float* __restrict__ xdbl,
        const float* __restrict__ xc,
        const float* __restrict__ xz,
        const float* __restrict__ A_log,
        const float* __restrict__ Dvec,
        const float* __restrict__ dtw,
        const float* __restrict__ dtb,
        float* __restrict__ y) {
    __shared__ float sB[TCHUNK][64];
    __shared__ float sC[TCHUNK][64];
    __shared__ float sx16[TCHUNK][16];
    __shared__ float2 sdx[TCHUNK][8];   // (dt, xc)
    __shared__ float sz[TCHUNK][8];
    __shared__ float sy[TCHUNK][8];
    __shared__ float sw[8][16];
    __shared__ float sbias[8];

    int b = blockIdx.x >> 6;
    int dbase = (blockIdx.x & 63) * 8;
    int wid = threadIdx.x >> 5;
    int lane = threadIdx.x & 31;
    int d = dbase + wid;

    if (threadIdx.x < 128) {
        int di = threadIdx.x >> 4, r = threadIdx.x & 15;
        sw[di][r] = dtw[(dbase + di) * DTR + r];
        if (r == 0) sbias[di] = dtb[dbase + di];
    }
    float A0 = -__expf(A_log[d * DS + lane]);
    float A1 = -__expf(A_log[d * DS + lane + 32]);
    float Dd = Dvec[d];
    float h0 = 0.0f, h1 = 0.0f;

    for (int t0 = 0; t0 < LSEQ; t0 += TCHUNK) {
        for (int i = threadIdx.x; i < TCHUNK * 128; i += 256) {
            int tt = i >> 7;
            int c = i & 127;
            float v = xdbl[(size_t)(b * LSEQ + t0 + tt) * XDBLW + DTR + c];
            if (c < 64) sB[tt][c] = v; else sC[tt][c - 64] = v;
        }
        for (int i = threadIdx.x; i < TCHUNK * 16; i += 256) {
            int tt = i >> 4, r = i & 15;
            sx16[tt][r] = xdbl[(size_t)(b * LSEQ + t0 + tt) * XDBLW + r];
        }
        for (int i = threadIdx.x; i < TCHUNK * 8; i += 256) {
            int tt = i >> 3, di = i & 7;
            size_t bt = (size_t)(b * LSEQ + t0 + tt);
            sdx[tt][di].y = xc[bt * DI + dbase + di];
            sz[tt][di]    = xz[bt * (2 * DI) + DI + dbase + di];
        }
        __syncthreads();
        for (int i = threadIdx.x; i < TCHUNK * 8; i += 256) {
            int tt = i >> 3, di = i & 7;
            float acc = sbias[di];
            #pragma unroll
            for (int r = 0; r < 16; r++) acc = fmaf(sx16[tt][r], sw[di][r], acc);
            sdx[tt][di].x = (acc > 20.0f) ? acc : __logf(1.0f + __expf(acc));
        }
        __syncthreads();

        #pragma unroll 1
        for (int g = 0; g < TCHUNK / 32; g++) {
            float part[32];
            #pragma unroll
            for (int j = 0; j < 32; j++) {
                int tt = g * 32 + j;
                float2 dx = sdx[tt][wid];
                float du = dx.x * dx.y;
                float dA0 = __expf(dx.x * A0);
                float dA1 = __expf(dx.x * A1);
                h0 = fmaf(dA0, h0, du * sB[tt][lane]);
                h1 = fmaf(dA1, h1, du * sB[tt][lane + 32]);
                part[j] = fmaf(h0, sC[tt][lane], h1 * sC[tt][lane + 32]);
            }
            #pragma unroll
            for (int s = 16; s >= 1; s >>= 1) {
                bool up = (lane & s) != 0;
                #pragma unroll
                for (int i2 = 0; i2 < 16; i2++) {
                    if (i2 >= s) break;
                    float keep = up ? part[i2 + s] : part[i2];
                    float send = up ? part[i2] : part[i2 + s];
                    part[i2] = keep + __shfl_xor_sync(0xffffffffu, send, s);
                }
            }
            int tt = g * 32 + lane;
            float2 dx = sdx[tt][wid];
            float zv = sz[tt][wid];
            float gate = zv / (1.0f + __expf(-zv));
            sy[tt][wid] = fmaf(dx.y, Dd, part[0]) * gate;
        }
        __syncthreads();
        for (int i = threadIdx.x; i < TCHUNK * 8; i += 256) {
            int tt = i >> 3, di = i & 7;
            y[(size_t)(b * LSEQ + t0 + tt) * DI + dbase + di] = sy[tt][di];
        }
        __syncthreads();
    }
}

// ---------------------------------------------------------------------------
// Forward 2048-pt FFT (DIF, natural -> bit-reversed), real input.
// 4 channels per block (128 blocks), float4 global I/O, padded stride 2049.
// ---------------------------------------------------------------------------
#define FSTR 2049
#define FFT_SMEM (2 * 4 * FSTR * 4)

__global__ void __launch_bounds__(512) fft_fwd_kernel(const float* __restrict__ xin,
                                                      float* __restrict__ dR,
                                                      float* __restrict__ dI) {
    extern __shared__ float sm[];
    float* sr = sm;
    float* si = sm + 4 * FSTR;
    int b = blockIdx.x >> 6;
    int c0 = (blockIdx.x & 63) * 4;
    size_t base = (size_t)b * LSEQ * DIMC + c0;
    int tid = threadIdx.x;

    for (int n = tid; n < 2048; n += 512) {
        float4 v = *(const float4*)(xin + base + (size_t)n * DIMC);
        sr[0 * FSTR + n] = v.x; sr[1 * FSTR + n] = v.y;
        sr[2 * FSTR + n] = v.z; sr[3 * FSTR + n] = v.w;
        si[0 * FSTR + n] = 0.0f; si[1 * FSTR + n] = 0.0f;
        si[2 * FSTR + n] = 0.0f; si[3 * FSTR + n] = 0.0f;
    }
    __syncthreads();

    #pragma unroll
    for (int hb = 10; hb >= 0; hb--) {
        int half = 1 << hb;
        float th = -PI_F / (float)half;
        for (int e = tid; e < 4096; e += 512) {
            int col = e >> 10, idx = e & 1023;
            int j = idx & (half - 1);
            int pos = ((idx >> hb) << (hb + 1)) + j;
            float* cr = sr + col * FSTR;
            float* ci = si + col * FSTR;
            float ar = cr[pos],        ai = ci[pos];
            float br = cr[pos + half], bi = ci[pos + half];
            float wi, wr;
            __sincosf(th * (float)j, &wi, &wr);
            float xr = ar - br, xi = ai - bi;
            cr[pos] = ar + br;  ci[pos] = ai + bi;
            cr[pos + half] = xr * wr - xi * wi;
            ci[pos + half] = xr * wi + xi * wr;
        }
        __syncthreads();
    }

    for (int n = tid; n < 2048; n += 512) {
        float4 vr, vi;
        vr.x = sr[0 * FSTR + n]; vr.y = sr[1 * FSTR + n];
        vr.z = sr[2 * FSTR + n]; vr.w = sr[3 * FSTR + n];
        vi.x = si[0 * FSTR + n]; vi.y = si[1 * FSTR + n];
        vi.z = si[2 * FSTR + n]; vi.w = si[3 * FSTR + n];
        *(float4*)(dR + base + (size_t)n * DIMC) = vr;
        *(float4*)(dI + base + (size_t)n * DIMC) = vi;
    }
}

// ---------------------------------------------------------------------------
// Inverse 2048-pt FFT (DIT, bit-reversed -> natural); real part + residual.
// ---------------------------------------------------------------------------
__global__ void __launch_bounds__(512) fft_inv_kernel(const float* __restrict__ dR,
                                                      const float* __restrict__ dI,
                                                      const float* __restrict__ x1,
                                                      float* __restrict__ out) {
    extern __shared__ float sm[];
    float* sr = sm;
    float* si = sm + 4 * FSTR;
    int b = blockIdx.x >> 6;
    int c0 = (blockIdx.x & 63) * 4;
    size_t base = (size_t)b * LSEQ * DIMC + c0;
    int tid = threadIdx.x;

    for (int n = tid; n < 2048; n += 512) {
        float4 vr = *(const float4*)(dR + base + (size_t)n * DIMC);
        float4 vi = *(const float4*)(dI + base + (size_t)n * DIMC);
        sr[0 * FSTR + n] = vr.x; sr[1 * FSTR + n] = vr.y;
        sr[2 * FSTR + n] = vr.z; sr[3 * FSTR + n] = vr.w;
        si[0 * FSTR + n] = vi.x; si[1 * FSTR + n] = vi.y;
        si[2 * FSTR + n] = vi.z; si[3 * FSTR + n] = vi.w;
    }
    __syncthreads();

    #pragma unroll
    for (int hb = 0; hb <= 10; hb++) {
        int half = 1 << hb;
        float th = PI_F / (float)half;
        for (int e = tid; e < 4096; e += 512) {
            int col = e >> 10, idx = e & 1023;
            int j = idx & (half - 1);
            int pos = ((idx >> hb) << (hb + 1)) + j;
            float* cr = sr + col * FSTR;
            float* ci = si + col * FSTR;
            float ar = cr[pos],        ai = ci[pos];
            float br = cr[pos + half], bi = ci[pos + half];
            float wi, wr;
            __sincosf(th * (float)j, &wi, &wr);
            float tr = br * wr - bi * wi;
            float ti = br * wi + bi * wr;
            cr[pos] = ar + tr;         ci[pos] = ai + ti;
            cr[pos + half] = ar - tr;  ci[pos + half] = ai - ti;
        }
        __syncthreads();
    }

    for (int n = tid; n < 2048; n += 512) {
        size_t a = base + (size_t)n * DIMC;
        float4 rx = *(const float4*)(x1 + a);
        float4 o;
        o.x = rx.x + sr[0 * FSTR + n];
        o.y = rx.y + sr[1 * FSTR + n];
        o.z = rx.z + sr[2 * FSTR + n];
        o.w = rx.w + sr[3 * FSTR + n];
        *(float4*)(out + a) = o;
    }
}

// ---------------------------------------------------------------------------
// EinFFT MLP with DFT4/IDFT4 over the NB axis folded in.
// ---------------------------------------------------------------------------
__global__ void __launch_bounds__(256) einfft_mlp_kernel(
        float* __restrict__ fR, float* __restrict__ fI,
        const float* __restrict__ cw1, const float* __restrict__ cb1,
        const float* __restrict__ cw2, const float* __restrict__ cb2) {
    __shared__ float sR[2048], sI[2048];
    __shared__ float tR[2048], tI[2048];
    int row0 = blockIdx.x * 8;
    int tid = threadIdx.x;
    for (int i = tid; i < 2048; i += 256) {
        sR[i] = fR[(size_t)row0 * DIMC + i];
        sI[i] = fI[(size_t)row0 * DIMC + i];
    }
    __syncthreads();

    const float sc = SQRT_INV_8192;
    #pragma unroll
    for (int g = tid; g < 512; g += 256) {
        int r = g >> 6, s = g & 63;
        int p = r * 256 + s;
        float r0 = sR[p],       i0 = sI[p];
        float r1 = sR[p + 64],  i1 = sI[p + 64];
        float r2 = sR[p + 128], i2 = sI[p + 128];
        float r3 = sR[p + 192], i3 = sI[p + 192];
        sR[p]       = (r0 + r1 + r2 + r3) * sc;
        sI[p]       = (i0 + i1 + i2 + i3) * sc;
        sR[p + 64]  = (r0 + i1 - r2 - i3) * sc;
        sI[p + 64]  = (i0 - r1 - i2 + r3) * sc;
        sR[p + 128] = (r0 - r1 + r2 - r3) * sc;
        sI[p + 128] = (i0 - i1 + i2 - i3) * sc;
        sR[p + 192] = (r0 - i1 - r2 + i3) * sc;
        sI[p + 192] = (i0 + r1 - i2 - r3) * sc;
    }
    __syncthreads();

    int k = tid >> 6, o = tid & 63;

    {
        const float* w0 = cw1 + k * 4096;
        const float* w1 = cw1 + 16384 + k * 4096;
        float bR = cb1[k * 64 + o];
        float bI = cb1[256 + k * 64 + o];
        float aR[8], aI[8];
        #pragma unroll
        for (int r = 0; r < 8; r++) { aR[r] = bR; aI[r] = bI; }
        for (int dd = 0; dd < 64; dd++) {
            float wa = w0[dd * 64 + o];
            float wb = w1[dd * 64 + o];
            int sb = k * 64 + dd;
            #pragma unroll
            for (int r = 0; r < 8; r++) {
                float xr = sR[r * 256 + sb];
                float xi = sI[r * 256 + sb];
                aR[r] = fmaf(xr, wa, fmaf(-xi, wb, aR[r]));
                aI[r] = fmaf(xr, wb, fmaf( xi, wa, aI[r]));
            }
        }
        #pragma unroll
        for (int r = 0; r < 8; r++) {
            tR[r * 256 + tid] = fmaxf(aR[r], 0.0f);
            tI[r * 256 + tid] = fmaxf(aI[r], 0.0f);
        }
    }
    __syncthreads();

    {
        const float* w0 = cw2 + k * 4096;
        const float* w1 = cw2 + 16384 + k * 4096;
        float bR = cb2[k * 64 + o];
        float bI = cb2[256 + k * 64 + o];
        float aR[8], aI[8];
        #pragma unroll
        for (int r = 0; r < 8; r++) { aR[r] = bR; aI[r] = bI; }
        for (int dd = 0; dd < 64; dd++) {
            float wa = w0[dd * 64 + o];
            float wb = w1[dd * 64 + o];
            int sb = k * 64 + dd;
            #pragma unroll
            for (int r = 0; r < 8; r++) {
                float xr = tR[r * 256 + sb];
                float xi = tI[r * 256 + sb];
                aR[r] = fmaf(xr, wa, fmaf(-xi, wb, aR[r]));
                aI[r] = fmaf(xr, wb, fmaf( xi, wa, aI[r]));
            }
        }
        #pragma unroll
        for (int r = 0; r < 8; r++) {
            float vR = aR[r], vI = aI[r];
            vR = (vR > LAMBDA_SS) ? vR - LAMBDA_SS
                 : ((vR < -LAMBDA_SS) ? vR + LAMBDA_SS : 0.0f);
            vI = (vI > LAMBDA_SS) ? vI - LAMBDA_SS
                 : ((vI < -LAMBDA_SS) ? vI + LAMBDA_SS : 0.0f);
            sR[r * 256 + tid] = vR;
            sI[r * 256 + tid] = vI;
        }
    }
    __syncthreads();

    #pragma unroll
    for (int g = tid; g < 512; g += 256) {
        int r = g >> 6, s = g & 63;
        int p = r * 256 + s;
        float R0 = sR[p],       I0 = sI[p];
        float R1 = sR[p + 64],  I1 = sI[p + 64];
        float R2 = sR[p + 128], I2 = sI[p + 128];
        float R3 = sR[p + 192], I3 = sI[p + 192];
        sR[p]       = (R0 + R1 + R2 + R3) * sc;
        sI[p]       = (I0 + I1 + I2 + I3) * sc;
        sR[p + 64]  = (R0 - I1 - R2 + I3) * sc;
        sI[p + 64]  = (I0 + R1 - I2 - R3) * sc;
        sR[p + 128] = (R0 - R1 + R2 - R3) * sc;
        sI[p + 128] = (I0 - I1 + I2 - I3) * sc;
        sR[p + 192] = (R0 + I1 - R2 - I3) * sc;
        sI[p + 192] = (I0 - R1 - I2 + R3) * sc;
    }
    __syncthreads();

    for (int i = tid; i < 2048; i += 256) {
        fR[(size_t)row0 * DIMC + i] = sR[i];
        fI[(size_t)row0 * DIMC + i] = sI[i];
    }
}

// ---------------------------------------------------------------------------
// Launch
// ---------------------------------------------------------------------------
extern "C" void kernel_launch(void* const* d_in, const int* in_sizes, int n_in,
                              void* d_out, int out_size) {
    const float* x         = (const float*)d_in[0];
    const float* norm1_w   = (const float*)d_in[1];
    const float* norm1_b   = (const float*)d_in[2];
    const float* in_proj_w = (const float*)d_in[3];
    const float* conv_w    = (const float*)d_in[4];
    const float* conv_b    = (const float*)d_in[5];
    const float* x_proj_w  = (const float*)d_in[6];
    const float* dt_proj_w = (const float*)d_in[7];
    const float* dt_proj_b = (const float*)d_in[8];
    const float* A_log     = (const float*)d_in[9];
    const float* Dvec      = (const float*)d_in[10];
    const float* out_proj_w= (const float*)d_in[11];
    const float* norm2_w   = (const float*)d_in[12];
    const float* norm2_b   = (const float*)d_in[13];
    const float* cw1       = (const float*)d_in[14];
    const float* cb1       = (const float*)d_in[15];
    const float* cw2       = (const float*)d_in[16];
    const float* cb2       = (const float*)d_in[17];
    float* out = (float*)d_out;

    void* sp = nullptr;
    cudaGetSymbolAddress(&sp, SCRATCH);
    float* S = (float*)sp;
    float* s_xn   = S + O_XN;
    float* s_xz   = S + O_XZ;
    float* s_xc   = S + O_XC;
    float* s_xdbl = S + O_XDBL;
    float* s_y    = S + O_Y;
    float* s_x1   = S + O_X1;
    float* s_xn2  = S + O_XN2;
    float* s_fr   = S + O_FR;
    float* s_fi   = S + O_FI;

    static int attr_done = 0;
    if (!attr_done) {
        cudaFuncSetAttribute(fft_fwd_kernel,
                             cudaFuncAttributeMaxDynamicSharedMemorySize, FFT_SMEM);
        cudaFuncSetAttribute(fft_inv_kernel,
                             cudaFuncAttributeMaxDynamicSharedMemorySize, FFT_SMEM);
        cudaFuncSetAttribute(gemm_tf32,
                             cudaFuncAttributeMaxDynamicSharedMemorySize, GEMM_SMEM);
        attr_done = 1;
    }

    // 1) LN1
    ln_kernel<<<NTOK / 8, 256>>>(x, norm1_w, norm1_b, s_xn);
    // 2) in_proj
    gemm_tf32<<<dim3((2 * DI) / GBN, NTOK / GBM), 256, GEMM_SMEM>>>(
        s_xn, in_proj_w, nullptr, s_xz, NTOK, 2 * DI, DIMC);
    // 3) conv + silu
    conv_silu_kernel<<<(NTOK * DI) / 256, 256>>>(s_xz, conv_w, conv_b, s_xc);
    // 4) x_proj
    gemm_tf32<<<dim3((XDBLW + GBN - 1) / GBN, NTOK / GBM), 256, GEMM_SMEM>>>(
        s_xc, x_proj_w, nullptr, s_xdbl, NTOK, XDBLW, DI);
    // 5) selective scan (fused dt + D-skip + silu(z) gate)
    scan_kernel<<<BATCH * (DI / 8), 256>>>(s_xdbl, s_xc, s_xz, A_log, Dvec,
                                           dt_proj_w, dt_proj_b, s_y);
    // 6) out_proj + residual
    gemm_tf32<<<dim3(DIMC / GBN, NTOK / GBM), 256, GEMM_SMEM>>>(
        s_y, out_proj_w, x, s_x1, NTOK, DIMC, DI);
    // 7) LN2
    ln_kernel<<<NTOK / 8, 256>>>(s_x1, norm2_w, norm2_b, s_xn2);
    // 8) forward FFT (4 ch/block, 128 blocks)
    fft_fwd_kernel<<<128, 512, FFT_SMEM>>>(s_xn2, s_fr, s_fi);
    // 9) fused EinFFT MLP (DFT4 + relu + softshrink + IDFT4)
    einfft_mlp_kernel<<<NTOK / 8, 256>>>(s_fr, s_fi, cw1, cb1, cw2, cb2);
    // 10) inverse FFT + residual -> out
    fft_inv_kernel<<<128, 512, FFT_SMEM>>>(s_fr, s_fi, s_x1, out);
}